// round 13
// baseline (speedup 1.0000x reference)
#include <cuda_runtime.h>
#include <cuda_fp16.h>
#include <math.h>
#include <stdint.h>

#define BATCH 32
#define CH    256
#define EMB   256
#define NHEAD 8
#define SHFT  4
#define TT    64
#define TOTW  2048
#define MROWS 131072
#define HID   768

// ---------------- scratch ----------------
__device__ float  g_qkv[(size_t)MROWS * 768];   // fp16 alias: qkv out; later mlp1 out
__device__ float  g_h  [(size_t)MROWS * 256];   // fp16 alias: proj out
__device__ __half g_qh [(size_t)MROWS * 256];   // fp16 copy of query (pixel layout)
__device__ __half g_oh [(size_t)MROWS * 256];   // attn out; later mlp2 out (fp16)
__device__ __half g_x2h[(size_t)MROWS * 256];   // ln1 out / residual (fp16)
__device__ __half g_wqkvT[768 * 256];
__device__ float  g_bqkv [768];
__device__ __half g_woT  [256 * 256];
__device__ __half g_w1T  [768 * 256];
__device__ __half g_w2T  [256 * 768];
__device__ __half g_bm   [64 * 8 * 64 * 64];    // fp16 bias+mask [win][head][t][s]

// row (window*64+token) -> pixel index in original query (folds roll by -S)
__device__ __forceinline__ int map_row(int row) {
    int w  = row >> 6;
    int t  = row & 63;
    int b  = w >> 6;
    int wi = w & 63;
    int hb = wi >> 3, wb = wi & 7;
    int i  = ((hb << 3) + (t >> 3) + SHFT) & 63;
    int j  = ((wb << 3) + (t & 7) + SHFT) & 63;
    return (b << 12) + (i << 6) + j;
}

__device__ __forceinline__ uint32_t smem_u32(const void* p) {
    uint32_t a;
    asm("{ .reg .u64 t; cvta.to.shared.u64 t, %1; cvt.u32.u64 %0, t; }" : "=r"(a) : "l"(p));
    return a;
}

__device__ __forceinline__ float tanh_fast(float x) {
    float r;
    asm("tanh.approx.f32 %0, %1;" : "=f"(r) : "f"(x));
    return r;
}

__device__ __forceinline__ uint32_t h2pack(float lo, float hi) {
    __half2 h = __floats2half2_rn(lo, hi);
    return *(uint32_t*)&h;
}

#define LDMX4(r0, r1, r2, r3, addr) \
    asm volatile("ldmatrix.sync.aligned.m8n8.x4.shared.b16 {%0,%1,%2,%3}, [%4];" \
        : "=r"(r0), "=r"(r1), "=r"(r2), "=r"(r3) : "r"(addr))

#define MMA_F16(d, a0, a1, a2, a3, b0, b1) \
    asm volatile("mma.sync.aligned.m16n8k16.row.col.f32.f16.f16.f32 " \
        "{%0,%1,%2,%3}, {%4,%5,%6,%7}, {%8,%9}, {%0,%1,%2,%3};" \
        : "+f"((d)[0]), "+f"((d)[1]), "+f"((d)[2]), "+f"((d)[3]) \
        : "r"(a0), "r"(a1), "r"(a2), "r"(a3), "r"(b0), "r"(b1))

#define CP_ASYNC16(dst, src) \
    asm volatile("cp.async.cg.shared.global [%0], [%1], 16;" :: "r"(dst), "l"(src))
#define CP_COMMIT()  asm volatile("cp.async.commit_group;" ::: "memory")
#define CP_WAIT1()   asm volatile("cp.async.wait_group 1;" ::: "memory")

#define QSCALE 0.17677669529663687f

// ================================================================================
// A-resident GEMM, 64x64 warp tiles (K = 256): C[M, NX*128] = A @ Bt^T + bias
// CTA owns 128 rows; per pipeline stage computes a 256-col n-step k16x4 slab.
// 8 warps 2m x 4n, warp tile 64x64 (4mt x 8nt mma). A resident 64KB; B 3x32KB.
// LDSM per kc per warp: 4 A + 4 B for 32 mma -> 128 B/mma (perimeter floor).
// ================================================================================
#define NRES_SMEM (65536 + 3 * 32768)

template<bool GATHER, bool GELU, int NX>
__global__ __launch_bounds__(256, 1)
void gemm_nres(const __half* __restrict__ A, const __half* __restrict__ Bt,
               const float* __restrict__ bias, __half* __restrict__ C)
{
    constexpr int N = NX * 128;
    static_assert((NX & 1) == 0, "NX must be even");
    extern __shared__ float smem[];
    const uint32_t sbase = smem_u32(smem);
    const uint32_t sBb   = sbase + 65536;
    const int tid  = threadIdx.x;
    const int lane = tid & 31;
    const int wid  = tid >> 5;
    const int warp_m = wid & 1;           // 0..1 (64-row halves)
    const int warp_n = wid >> 1;          // 0..3 (64-col quarters of 256-col step)
    const int row0 = blockIdx.x * 128;

    const int mrow = tid >> 3;            // 0..31
    const int c8   = tid & 7;
    const uint32_t swc = (uint32_t)((c8 ^ (mrow & 7)) << 4);

    // B loader: 8 rows per thread (256-row B tile per stage)
    const __half* bcol = Bt + (size_t)mrow * 256 + c8 * 8;   // + i*32*256
    uint32_t stO[8];
#pragma unroll
    for (int i = 0; i < 8; i++)
        stO[i] = (uint32_t)((mrow + 32 * i) * 128) + swc;

    // ---- prologue: group0 = A (4 slabs, 16 cp) + B stage0 (8 cp); group1 = B stage1
    {
        const __half* arow[4];
#pragma unroll
        for (int i = 0; i < 4; i++) {
            const int m = mrow + 32 * i;
            arow[i] = (GATHER ? (A + (size_t)map_row(row0 + m) * CH)
                              : (A + (size_t)(row0 + m) * 256)) + c8 * 8;
        }
#pragma unroll
        for (int t = 0; t < 4; t++)
#pragma unroll
            for (int i = 0; i < 4; i++)
                CP_ASYNC16(sbase + t * 16384 + stO[i], arow[i] + t * 64);
#pragma unroll
        for (int i = 0; i < 8; i++)                            // stage 0 -> buf 0
            CP_ASYNC16(sBb + stO[i], bcol + (size_t)i * 32 * 256);
        CP_COMMIT();
#pragma unroll
        for (int i = 0; i < 8; i++)                            // stage 1 -> buf 1
            CP_ASYNC16(sBb + 32768 + stO[i], bcol + (size_t)i * 32 * 256 + 64);
        CP_COMMIT();
    }

    const int rA  = warp_m * 64 + (lane & 15);
    const int hiA = lane >> 4;
    const int xA  = lane & 7;
    const int rB  = warp_n * 64 + ((lane >> 4) << 3) + (lane & 7);  // + p*16
    const int hiB = (lane >> 3) & 1;
    const int xB  = lane & 7;

    float acc[4][8][4];
#pragma unroll
    for (int i = 0; i < 4; i++)
#pragma unroll
        for (int j = 0; j < 8; j++)
#pragma unroll
            for (int e = 0; e < 4; e++) acc[i][j][e] = 0.f;

    constexpr int S = (NX / 2) * 4;        // 4 k-slabs per 256-col n-step
#pragma unroll 4
    for (int s = 0; s < S; ++s) {
        CP_WAIT1();
        __syncthreads();

        // prefetch stage s+2 into buf (s+2)%3
        const int sp = s + 2;
        if (sp < S) {
            const int nsp = sp >> 2, tp = sp & 3;
            const size_t off = (size_t)nsp * (256 * 256) + tp * 64;
            const uint32_t so = sBb + (uint32_t)(sp % 3) * 32768;
#pragma unroll
            for (int i = 0; i < 8; i++)
                CP_ASYNC16(so + stO[i], bcol + (size_t)i * 32 * 256 + off);
        }
        CP_COMMIT();

        const uint32_t sa = sbase + (uint32_t)(s & 3) * 16384;
        const uint32_t sb = sBb   + (uint32_t)(s % 3) * 32768;
#pragma unroll
        for (int kc = 0; kc < 4; kc++) {
            uint32_t af[4][4];
#pragma unroll
            for (int mt = 0; mt < 4; mt++) {
                const uint32_t addr = sa + (uint32_t)((rA + mt * 16) * 128)
                                    + (uint32_t)((((kc << 1) + hiA) ^ xA) << 4);
                LDMX4(af[mt][0], af[mt][1], af[mt][2], af[mt][3], addr);
            }
            uint32_t bf[8][2];
#pragma unroll
            for (int p = 0; p < 4; p++) {
                const uint32_t addr = sb + (uint32_t)((rB + p * 16) * 128)
                                    + (uint32_t)((((kc << 1) + hiB) ^ xB) << 4);
                LDMX4(bf[2*p][0], bf[2*p][1], bf[2*p+1][0], bf[2*p+1][1], addr);
            }
#pragma unroll
            for (int mt = 0; mt < 4; mt++)
#pragma unroll
                for (int nt = 0; nt < 8; nt++)
                    MMA_F16(acc[mt][nt], af[mt][0], af[mt][1], af[mt][2], af[mt][3],
                            bf[nt][0], bf[nt][1]);
        }

        // epilogue at end of each 256-col n-step
        if ((s & 3) == 3) {
            const int col0 = (s >> 2) * 256;
            const int rbase = row0 + warp_m * 64 + (lane >> 2);
            const int cb0   = col0 + warp_n * 64 + 2 * (lane & 3);
#pragma unroll
            for (int nt = 0; nt < 8; nt++) {
                const int cc = cb0 + nt * 8;
                const float bv0 = bias[cc], bv1 = bias[cc + 1];
                const float post = (GATHER && cc < 256) ? QSCALE : 1.f;
#pragma unroll
                for (int mt = 0; mt < 4; mt++) {
                    const int r = rbase + mt * 16;
                    float v[4];
#pragma unroll
                    for (int e = 0; e < 4; e++) {
                        float x = acc[mt][nt][e] + ((e & 1) ? bv1 : bv0);
                        if (GELU) {
                            float x3 = x * x * x;
                            x = 0.5f * x * (1.f + tanh_fast(0.7978845608028654f * (x + 0.044715f * x3)));
                        }
                        v[e] = x * post;
                        acc[mt][nt][e] = 0.f;
                    }
                    *(__half2*)(C + (size_t)r * N + cc)       = __floats2half2_rn(v[0], v[1]);
                    *(__half2*)(C + (size_t)(r + 8) * N + cc) = __floats2half2_rn(v[2], v[3]);
                }
            }
        }
    }
}

// ---------------- fp16 mma.sync GEMM (frozen R8/R9) — used for mlp2 (K=768) ----
#define STAGE_BYTES 32768
#define NSTAGE      3
#define GEMM_SMEM   (NSTAGE * STAGE_BYTES)

__global__ __launch_bounds__(256, 2)
void gemm_mma(const __half* __restrict__ A, const __half* __restrict__ Bt,
              const float* __restrict__ bias, __half* __restrict__ C,
              int N, int Kd)
{
    extern __shared__ float smem[];
    const uint32_t sbase = smem_u32(smem);
    const int tid  = threadIdx.x;
    const int lane = tid & 31;
    const int wid  = tid >> 5;
    const int warp_m = wid >> 2;
    const int warp_n = wid & 3;
    const int row0 = blockIdx.y * 128;
    const int col0 = blockIdx.x * 128;

    const int mrow = tid >> 3;
    const int c8   = tid & 7;
    const uint32_t swc = (uint32_t)((c8 ^ (mrow & 7)) << 4);

    const __half* arow[4];
    const __half* brow[4];
    uint32_t stA[4];
#pragma unroll
    for (int i = 0; i < 4; i++) {
        const int m = mrow + 32 * i;
        arow[i] = A + (size_t)(row0 + m) * Kd + c8 * 8;
        brow[i] = Bt + (size_t)(col0 + m) * Kd + c8 * 8;
        stA[i] = (uint32_t)(m * 128) + swc;
    }

    const int rA  = warp_m * 64 + (lane & 15);
    const int hiA = lane >> 4;
    const int xA  = lane & 7;
    const int rB  = warp_n * 32 + ((lane >> 4) << 3) + (lane & 7);
    const int hiB = (lane >> 3) & 1;
    const int xB  = lane & 7;

    float acc[4][4][4];
#pragma unroll
    for (int i = 0; i < 4; i++)
#pragma unroll
        for (int j = 0; j < 4; j++)
#pragma unroll
            for (int e = 0; e < 4; e++) acc[i][j][e] = 0.f;

    const int T = Kd >> 6;

#pragma unroll
    for (int s = 0; s < NSTAGE - 1; s++) {
        const int k0 = s * 64;
        const uint32_t so = sbase + s * STAGE_BYTES;
#pragma unroll
        for (int i = 0; i < 4; i++) {
            CP_ASYNC16(so + stA[i],         arow[i] + k0);
            CP_ASYNC16(so + stA[i] + 16384, brow[i] + k0);
        }
        CP_COMMIT();
    }

    for (int t = 0; t < T; ++t) {
        CP_WAIT1();
        __syncthreads();

        const int kt = t + NSTAGE - 1;
        if (kt < T) {
            const int k0 = kt * 64;
            const uint32_t so = sbase + (kt % NSTAGE) * STAGE_BYTES;
#pragma unroll
            for (int i = 0; i < 4; i++) {
                CP_ASYNC16(so + stA[i],         arow[i] + k0);
                CP_ASYNC16(so + stA[i] + 16384, brow[i] + k0);
            }
        }
        CP_COMMIT();

        const uint32_t sa = sbase + (t % NSTAGE) * STAGE_BYTES;
        const uint32_t sb = sa + 16384;
#pragma unroll
        for (int kc = 0; kc < 4; kc++) {
            uint32_t af[4][4];
#pragma unroll
            for (int mt = 0; mt < 4; mt++) {
                const uint32_t addr = sa + (uint32_t)((rA + mt * 16) * 128)
                                    + (uint32_t)((((kc << 1) + hiA) ^ xA) << 4);
                LDMX4(af[mt][0], af[mt][1], af[mt][2], af[mt][3], addr);
            }
            uint32_t bf[4][2];
#pragma unroll
            for (int p = 0; p < 2; p++) {
                const uint32_t addr = sb + (uint32_t)((rB + p * 16) * 128)
                                    + (uint32_t)((((kc << 1) + hiB) ^ xB) << 4);
                LDMX4(bf[2*p][0], bf[2*p][1], bf[2*p+1][0], bf[2*p+1][1], addr);
            }
#pragma unroll
            for (int mt = 0; mt < 4; mt++)
#pragma unroll
                for (int nt = 0; nt < 4; nt++)
                    MMA_F16(acc[mt][nt], af[mt][0], af[mt][1], af[mt][2], af[mt][3],
                            bf[nt][0], bf[nt][1]);
        }
    }

    const int rbase = row0 + warp_m * 64 + (lane >> 2);
    const int cb0   = col0 + warp_n * 32 + 2 * (lane & 3);
#pragma unroll
    for (int nt = 0; nt < 4; nt++) {
        const int cc = cb0 + nt * 8;
        const float bv0 = bias[cc], bv1 = bias[cc + 1];
#pragma unroll
        for (int mt = 0; mt < 4; mt++) {
            const int r = rbase + mt * 16;
            float v[4];
#pragma unroll
            for (int e = 0; e < 4; e++)
                v[e] = acc[mt][nt][e] + ((e & 1) ? bv1 : bv0);
            *(__half2*)(C + (size_t)r * N + cc)       = __floats2half2_rn(v[0], v[1]);
            *(__half2*)(C + (size_t)(r + 8) * N + cc) = __floats2half2_rn(v[2], v[3]);
        }
    }
}

// ---------------- attention (frozen R10, fp16 bm) ------------------------------
#define AQ_STR 40
#define AV_STR 72

__global__ __launch_bounds__(128)
void attn_kernel(const __half* __restrict__ qkv, const __half* __restrict__ bm,
                 __half* __restrict__ o)
{
    const int w = blockIdx.x, head = blockIdx.y;
    const int tid = threadIdx.x;
    const int lane = tid & 31;
    const int wid  = tid >> 5;

    __shared__ __align__(16) __half sQ[64 * AQ_STR];
    __shared__ __align__(16) __half sK[64 * AQ_STR];
    __shared__ __align__(16) __half sVt[32 * AV_STR];

    {
        const int row  = tid >> 1;
        const int half16 = (tid & 1) * 16;
        const __half* base = qkv + (size_t)(w * 64 + row) * 768 + head * 32 + half16;
        uint4 qv0 = *(const uint4*)(base);
        uint4 qv1 = *(const uint4*)(base + 8);
        uint4 kv0 = *(const uint4*)(base + 256);
        uint4 kv1 = *(const uint4*)(base + 264);
        *(uint4*)(sQ + row * AQ_STR + half16)     = qv0;
        *(uint4*)(sQ + row * AQ_STR + half16 + 8) = qv1;
        *(uint4*)(sK + row * AQ_STR + half16)     = kv0;
        *(uint4*)(sK + row * AQ_STR + half16 + 8) = kv1;
        __half vv[16];
        *(uint4*)(vv)     = *(const uint4*)(base + 512);
        *(uint4*)(vv + 8) = *(const uint4*)(base + 520);
#pragma unroll
        for (int j = 0; j < 16; j++)
            sVt[(half16 + j) * AV_STR + row] = vv[j];
    }
    __syncthreads();

    const uint32_t sQb  = smem_u32(sQ);
    const uint32_t sKb  = smem_u32(sK);
    const uint32_t sVtb = smem_u32(sVt);

    const int rA  = (lane & 15);
    const int hiA = lane >> 4;
    const int rBl = ((lane >> 4) << 3) + (lane & 7);
    const int hiB = (lane >> 3) & 1;

    float acc[8][4];
#pragma unroll
    for (int nt = 0; nt < 8; nt++)
#pragma unroll
        for (int e = 0; e < 4; e++) acc[nt][e] = 0.f;

#pragma unroll
    for (int kc = 0; kc < 2; kc++) {
        uint32_t a0, a1, a2, a3;
        {
            const uint32_t addr = sQb + (uint32_t)(((wid * 16 + rA) * AQ_STR
                                   + kc * 16 + hiA * 8) * 2);
            LDMX4(a0, a1, a2, a3, addr);
        }
#pragma unroll
        for (int p = 0; p < 4; p++) {
            uint32_t b00, b01, b10, b11;
            const uint32_t addr = sKb + (uint32_t)(((p * 16 + rBl) * AQ_STR
                                   + kc * 16 + hiB * 8) * 2);
            LDMX4(b00, b01, b10, b11, addr);
            MMA_F16(acc[2*p],   a0, a1, a2, a3, b00, b01);
            MMA_F16(acc[2*p+1], a0, a1, a2, a3, b10, b11);
        }
    }

    const __half* bmr = bm + (size_t)((w & 63) * 8 + head) * 4096;
    const int r0 = wid * 16 + (lane >> 2);
    const int cb = 2 * (lane & 3);
#pragma unroll
    for (int nt = 0; nt < 8; nt++) {
        const float2 blo = __half22float2(*(const __half2*)(bmr + r0 * 64 + 8 * nt + cb));
        const float2 bhi = __half22float2(*(const __half2*)(bmr + (r0 + 8) * 64 + 8 * nt + cb));
        acc[nt][0] += blo.x; acc[nt][1] += blo.y;
        acc[nt][2] += bhi.x; acc[nt][3] += bhi.y;
    }
    float m0 = -1e30f, m1 = -1e30f;
#pragma unroll
    for (int nt = 0; nt < 8; nt++) {
        m0 = fmaxf(m0, fmaxf(acc[nt][0], acc[nt][1]));
        m1 = fmaxf(m1, fmaxf(acc[nt][2], acc[nt][3]));
    }
    m0 = fmaxf(m0, __shfl_xor_sync(0xffffffffu, m0, 1));
    m0 = fmaxf(m0, __shfl_xor_sync(0xffffffffu, m0, 2));
    m1 = fmaxf(m1, __shfl_xor_sync(0xffffffffu, m1, 1));
    m1 = fmaxf(m1, __shfl_xor_sync(0xffffffffu, m1, 2));

    float s0 = 0.f, s1 = 0.f;
#pragma unroll
    for (int nt = 0; nt < 8; nt++) {
        acc[nt][0] = __expf(acc[nt][0] - m0); s0 += acc[nt][0];
        acc[nt][1] = __expf(acc[nt][1] - m0); s0 += acc[nt][1];
        acc[nt][2] = __expf(acc[nt][2] - m1); s1 += acc[nt][2];
        acc[nt][3] = __expf(acc[nt][3] - m1); s1 += acc[nt][3];
    }
    s0 += __shfl_xor_sync(0xffffffffu, s0, 1);
    s0 += __shfl_xor_sync(0xffffffffu, s0, 2);
    s1 += __shfl_xor_sync(0xffffffffu, s1, 1);
    s1 += __shfl_xor_sync(0xffffffffu, s1, 2);
    const float inv0 = 1.f / s0, inv1 = 1.f / s1;

    float oacc[4][4];
#pragma unroll
    for (int nt = 0; nt < 4; nt++)
#pragma unroll
        for (int e = 0; e < 4; e++) oacc[nt][e] = 0.f;

#pragma unroll
    for (int kc = 0; kc < 4; kc++) {
        const uint32_t a0 = h2pack(acc[2*kc][0]   * inv0, acc[2*kc][1]   * inv0);
        const uint32_t a1 = h2pack(acc[2*kc][2]   * inv1, acc[2*kc][3]   * inv1);
        const uint32_t a2 = h2pack(acc[2*kc+1][0] * inv0, acc[2*kc+1][1] * inv0);
        const uint32_t a3 = h2pack(acc[2*kc+1][2] * inv1, acc[2*kc+1][3] * inv1);
#pragma unroll
        for (int p = 0; p < 2; p++) {
            uint32_t b00, b01, b10, b11;
            const uint32_t addr = sVtb + (uint32_t)(((p * 16 + rBl) * AV_STR
                                   + kc * 16 + hiB * 8) * 2);
            LDMX4(b00, b01, b10, b11, addr);
            MMA_F16(oacc[2*p],   a0, a1, a2, a3, b00, b01);
            MMA_F16(oacc[2*p+1], a0, a1, a2, a3, b10, b11);
        }
    }

    __half* obase = o + (size_t)(w * 64 + r0) * 256 + head * 32;
#pragma unroll
    for (int nt = 0; nt < 4; nt++) {
        *(__half2*)(obase + 8 * nt + cb) = __floats2half2_rn(oacc[nt][0], oacc[nt][1]);
        *(__half2*)(obase + 8 * 256 + 8 * nt + cb) = __floats2half2_rn(oacc[nt][2], oacc[nt][3]);
    }
}

// ---------------- LayerNorm: warp-per-row, fp16 inputs (frozen R10) ------------
__global__ __launch_bounds__(256)
void ln1_kernel(const __half* __restrict__ X, const float* __restrict__ g,
                const float* __restrict__ b, const float* __restrict__ query,
                __half* __restrict__ out)
{
    const int row  = blockIdx.x * 8 + (threadIdx.x >> 5);
    const int lane = threadIdx.x & 31;
    const int c0   = lane * 8;

    __half x8[8];
    *(uint4*)(x8) = *(const uint4*)(X + (size_t)row * CH + c0);
    float v[8];
#pragma unroll
    for (int i = 0; i < 8; i++) v[i] = __half2float(x8[i]);

    float s = 0.f, s2 = 0.f;
#pragma unroll
    for (int i = 0; i < 8; i++) { s += v[i]; s2 += v[i] * v[i]; }
#pragma unroll
    for (int off = 16; off; off >>= 1) {
        s  += __shfl_xor_sync(0xffffffffu, s,  off);
        s2 += __shfl_xor_sync(0xffffffffu, s2, off);
    }
    const float mean = s * (1.f / 256.f);
    const float rstd = rsqrtf(s2 * (1.f / 256.f) - mean * mean + 1e-5f);

    float gv[8], bv[8], qv[8];
    *(float4*)(gv)     = *(const float4*)(g + c0);
    *(float4*)(gv + 4) = *(const float4*)(g + c0 + 4);
    *(float4*)(bv)     = *(const float4*)(b + c0);
    *(float4*)(bv + 4) = *(const float4*)(b + c0 + 4);
    const float* qr = query + (size_t)map_row(row) * CH + c0;
    *(float4*)(qv)     = *(const float4*)(qr);
    *(float4*)(qv + 4) = *(const float4*)(qr + 4);

    __half h8[8];
#pragma unroll
    for (int i = 0; i < 8; i++)
        h8[i] = __float2half((v[i] - mean) * rstd * gv[i] + bv[i] + qv[i]);
    *(uint4*)(out + (size_t)row * CH + c0) = *(uint4*)h8;
}

__global__ __launch_bounds__(256)
void ln2_kernel(const __half* __restrict__ X, const float* __restrict__ g,
                const float* __restrict__ b, const __half* __restrict__ x2,
                float* __restrict__ out)
{
    const int row  = blockIdx.x * 8 + (threadIdx.x >> 5);
    const int lane = threadIdx.x & 31;
    const int c0   = lane * 8;

    __half x8[8];
    *(uint4*)(x8) = *(const uint4*)(X + (size_t)row * CH + c0);
    float v[8];
#pragma unroll
    for (int i = 0; i < 8; i++) v[i] = __half2float(x8[i]);

    float s = 0.f, s2 = 0.f;
#pragma unroll
    for (int i = 0; i < 8; i++) { s += v[i]; s2 += v[i] * v[i]; }
#pragma unroll
    for (int off = 16; off; off >>= 1) {
        s  += __shfl_xor_sync(0xffffffffu, s,  off);
        s2 += __shfl_xor_sync(0xffffffffu, s2, off);
    }
    const float mean = s * (1.f / 256.f);
    const float rstd = rsqrtf(s2 * (1.f / 256.f) - mean * mean + 1e-5f);

    float gv[8], bv[8];
    *(float4*)(gv)     = *(const float4*)(g + c0);
    *(float4*)(gv + 4) = *(const float4*)(g + c0 + 4);
    *(float4*)(bv)     = *(const float4*)(b + c0);
    *(float4*)(bv + 4) = *(const float4*)(b + c0 + 4);
    __half r8[8];
    *(uint4*)(r8) = *(const uint4*)(x2 + (size_t)row * CH + c0);

    float o8[8];
#pragma unroll
    for (int i = 0; i < 8; i++)
        o8[i] = (v[i] - mean) * rstd * gv[i] + bv[i] + __half2float(r8[i]);
    float* op = out + (size_t)map_row(row) * CH + c0;
    *(float4*)(op)     = *(float4*)(o8);
    *(float4*)(op + 4) = *(float4*)(o8 + 4);
}

// ---------------- weight prep ----------------------------------------------------
__global__ __launch_bounds__(256)
void prep_kernel(const float* __restrict__ wq, const float* __restrict__ wk,
                 const float* __restrict__ wv, const float* __restrict__ bq,
                 const float* __restrict__ bk, const float* __restrict__ bv,
                 const float* __restrict__ wo, const float* __restrict__ w1,
                 const float* __restrict__ w2,
                 __half* __restrict__ wqkvT, float* __restrict__ bqkv,
                 __half* __restrict__ woT, __half* __restrict__ w1T,
                 __half* __restrict__ w2T)
{
    int i = blockIdx.x * 256 + threadIdx.x;
    if (i < 196608) {
        int n = i >> 8, k = i & 255;
        float v = (n < 256) ? wq[k * 256 + n]
                : (n < 512) ? wk[k * 256 + (n - 256)]
                            : wv[k * 256 + (n - 512)];
        wqkvT[i] = __float2half(v);
    } else if (i < 262144) {
        int j = i - 196608; int n = j >> 8, k = j & 255;
        woT[j] = __float2half(wo[k * 256 + n]);
    } else if (i < 458752) {
        int j = i - 262144; int n = j >> 8, k = j & 255;
        w1T[j] = __float2half(w1[k * 768 + n]);
    } else if (i < 655360) {
        int j = i - 458752; int n = j / 768, k = j - n * 768;
        w2T[j] = __float2half(w2[k * 256 + n]);
    } else if (i < 656128) {
        int n = i - 655360;
        bqkv[n] = (n < 256) ? bq[n] : (n < 512) ? bk[n - 256] : bv[n - 512];
    }
}

// ---------------- query fp32 -> fp16 copy ----------------------------------------
__global__ __launch_bounds__(256)
void conv_query_kernel(const float* __restrict__ q, __half* __restrict__ qh)
{
    const int i = (blockIdx.x * 256 + threadIdx.x) * 4;
    float4 v = *(const float4*)(q + i);
    *(__half2*)(qh + i)     = __floats2half2_rn(v.x, v.y);
    *(__half2*)(qh + i + 2) = __floats2half2_rn(v.z, v.w);
}

// ---------------- bias+mask table (fp16, mask clamped to -3e4) -------------------
__global__ __launch_bounds__(256)
void prep_bm_kernel(const float* __restrict__ rpe, const float* __restrict__ mask,
                    const int* __restrict__ rel, __half* __restrict__ bm)
{
    int idx = blockIdx.x * 256 + threadIdx.x;
    int wi  = idx >> 15;
    int rem = idx & 32767;
    int h   = rem >> 12;
    int ts  = rem & 4095;
    bm[idx] = __float2half(rpe[rel[ts] * NHEAD + h] + fmaxf(mask[wi * 4096 + ts], -30000.f));
}

// ---------------- launch ----------------------------------------------------------
extern "C" void kernel_launch(void* const* d_in, const int* in_sizes, int n_in,
                              void* d_out, int out_size)
{
    const float* query = (const float*)d_in[0];
    const float* wq = (const float*)d_in[1];  const float* bq = (const float*)d_in[2];
    const float* wk = (const float*)d_in[3];  const float* bk = (const float*)d_in[4];
    const float* wv = (const float*)d_in[5];  const float* bv = (const float*)d_in[6];
    const float* wo = (const float*)d_in[7];  const float* bo = (const float*)d_in[8];
    const float* rpe = (const float*)d_in[9];
    const float* ln1g = (const float*)d_in[10]; const float* ln1b = (const float*)d_in[11];
    const float* ln2g = (const float*)d_in[12]; const float* ln2b = (const float*)d_in[13];
    const float* w1 = (const float*)d_in[14]; const float* b1 = (const float*)d_in[15];
    const float* w2 = (const float*)d_in[16]; const float* b2 = (const float*)d_in[17];
    const float* amask = (const float*)d_in[18];
    const int*   rel   = (const int*)d_in[19];
    float* out = (float*)d_out;

    float *qkvf, *hf, *bqkv;
    __half *qh, *oh, *x2h, *wqkvT, *woT, *w1T, *w2T, *bm;
    cudaGetSymbolAddress((void**)&qkvf,  g_qkv);
    cudaGetSymbolAddress((void**)&hf,    g_h);
    cudaGetSymbolAddress((void**)&qh,    g_qh);
    cudaGetSymbolAddress((void**)&oh,    g_oh);
    cudaGetSymbolAddress((void**)&x2h,   g_x2h);
    cudaGetSymbolAddress((void**)&wqkvT, g_wqkvT);
    cudaGetSymbolAddress((void**)&bqkv,  g_bqkv);
    cudaGetSymbolAddress((void**)&woT,   g_woT);
    cudaGetSymbolAddress((void**)&w1T,   g_w1T);
    cudaGetSymbolAddress((void**)&w2T,   g_w2T);
    cudaGetSymbolAddress((void**)&bm,    g_bm);
    __half* qkvh = (__half*)qkvf;   // fp16 qkv / mlp1 alias
    __half* hh   = (__half*)hf;     // fp16 proj-out alias

    cudaFuncSetAttribute(gemm_nres<true,  false, 6>, cudaFuncAttributeMaxDynamicSharedMemorySize, NRES_SMEM);
    cudaFuncSetAttribute(gemm_nres<false, false, 2>, cudaFuncAttributeMaxDynamicSharedMemorySize, NRES_SMEM);
    cudaFuncSetAttribute(gemm_nres<false, true,  6>, cudaFuncAttributeMaxDynamicSharedMemorySize, NRES_SMEM);
    cudaFuncSetAttribute(gemm_mma, cudaFuncAttributeMaxDynamicSharedMemorySize, GEMM_SMEM);

    // prep: weights->fp16, bias/mask table (fp16), query->fp16
    prep_kernel<<<2563, 256>>>(wq, wk, wv, bq, bk, bv, wo, w1, w2,
                               wqkvT, bqkv, woT, w1T, w2T);
    prep_bm_kernel<<<8192, 256>>>(rpe, amask, rel, bm);
    conv_query_kernel<<<32768, 256>>>(query, qh);

    // fused QKV projection (A-resident, 64x64 warp tiles; q scaled in epilogue)
    gemm_nres<true,  false, 6><<<1024, 256, NRES_SMEM>>>(qh, wqkvT, bqkv, qkvh);

    // windowed attention -> fp16 oh
    attn_kernel<<<dim3(TOTW, NHEAD), 128>>>(qkvh, bm, oh);

    // output projection (A-resident) -> fp16 hh
    gemm_nres<false, false, 2><<<1024, 256, NRES_SMEM>>>(oh, woT, bo, hh);

    // LN1 + residual -> fp16 x2
    ln1_kernel<<<MROWS / 8, 256>>>(hh, ln1g, ln1b, query, x2h);

    // MLP: gelu(x2@w1+b1) -> fp16 (A-resident); @w2+b2 (K=768) -> fp16 oh
    gemm_nres<false, true,  6><<<1024, 256, NRES_SMEM>>>(x2h, w1T, b1, qkvh);
    gemm_mma<<<dim3(2, 1024), 256, GEMM_SMEM>>>(qkvh, w2T, b2, oh, 256, 768);

    // LN2 + residual, scatter to output
    ln2_kernel<<<MROWS / 8, 256>>>(oh, ln2g, ln2b, x2h, out);
}

// round 14
// speedup vs baseline: 1.0800x; 1.0800x over previous
#include <cuda_runtime.h>
#include <cuda_fp16.h>
#include <math.h>
#include <stdint.h>

#define BATCH 32
#define CH    256
#define EMB   256
#define NHEAD 8
#define SHFT  4
#define TT    64
#define TOTW  2048
#define MROWS 131072
#define HID   768

// ---------------- scratch ----------------
__device__ float  g_qkv[(size_t)MROWS * 768];   // fp16 alias: qkv out; later mlp1 out
__device__ float  g_h  [(size_t)MROWS * 256];   // fp16 alias: proj out
__device__ __half g_oh [(size_t)MROWS * 256];   // attn out; later mlp2 out (fp16)
__device__ __half g_x2h[(size_t)MROWS * 256];   // ln1 out / residual (fp16)
__device__ __half g_wqkvT[768 * 256];
__device__ float  g_bqkv [768];
__device__ __half g_woT  [256 * 256];
__device__ __half g_w1T  [768 * 256];
__device__ __half g_w2T  [256 * 768];
__device__ __half g_bm   [64 * 8 * 64 * 64];    // fp16 bias+mask [win][head][t][s]

// row (window*64+token) -> pixel index in original query (folds roll by -S)
__device__ __forceinline__ int map_row(int row) {
    int w  = row >> 6;
    int t  = row & 63;
    int b  = w >> 6;
    int wi = w & 63;
    int hb = wi >> 3, wb = wi & 7;
    int i  = ((hb << 3) + (t >> 3) + SHFT) & 63;
    int j  = ((wb << 3) + (t & 7) + SHFT) & 63;
    return (b << 12) + (i << 6) + j;
}

__device__ __forceinline__ uint32_t smem_u32(const void* p) {
    uint32_t a;
    asm("{ .reg .u64 t; cvta.to.shared.u64 t, %1; cvt.u32.u64 %0, t; }" : "=r"(a) : "l"(p));
    return a;
}

__device__ __forceinline__ float tanh_fast(float x) {
    float r;
    asm("tanh.approx.f32 %0, %1;" : "=f"(r) : "f"(x));
    return r;
}

__device__ __forceinline__ uint32_t h2pack(float lo, float hi) {
    __half2 h = __floats2half2_rn(lo, hi);
    return *(uint32_t*)&h;
}

#define LDMX4(r0, r1, r2, r3, addr) \
    asm volatile("ldmatrix.sync.aligned.m8n8.x4.shared.b16 {%0,%1,%2,%3}, [%4];" \
        : "=r"(r0), "=r"(r1), "=r"(r2), "=r"(r3) : "r"(addr))

#define MMA_F16(d, a0, a1, a2, a3, b0, b1) \
    asm volatile("mma.sync.aligned.m16n8k16.row.col.f32.f16.f16.f32 " \
        "{%0,%1,%2,%3}, {%4,%5,%6,%7}, {%8,%9}, {%0,%1,%2,%3};" \
        : "+f"((d)[0]), "+f"((d)[1]), "+f"((d)[2]), "+f"((d)[3]) \
        : "r"(a0), "r"(a1), "r"(a2), "r"(a3), "r"(b0), "r"(b1))

#define CP_ASYNC16(dst, src) \
    asm volatile("cp.async.cg.shared.global [%0], [%1], 16;" :: "r"(dst), "l"(src))
#define CP_COMMIT()  asm volatile("cp.async.commit_group;" ::: "memory")
#define CP_WAIT1()   asm volatile("cp.async.wait_group 1;" ::: "memory")

#define QSCALE 0.17677669529663687f

// ================================================================================
// A-resident N-looped GEMM (K = 256 fixed): C[M, NX*128] = A[M,256] @ Bt^T + bias
// CTA owns 128 rows; A (128x256 fp16 = 64KB) resident; B triple-buffered 16KB
// stages (R12-proven config). 8 warps 2m x 4n, warp tile 64x32.
// GATHER: A rows gathered from fp32 query via map_row, converted fp16 in-prologue.
// ================================================================================
#define NRES_SMEM (65536 + 3 * 16384)

template<bool GATHER, bool GELU, int NX>
__global__ __launch_bounds__(256, 2)
void gemm_nres(const void* __restrict__ Ain, const __half* __restrict__ Bt,
               const float* __restrict__ bias, __half* __restrict__ C)
{
    constexpr int N = NX * 128;
    extern __shared__ float smem[];
    const uint32_t sbase = smem_u32(smem);
    const uint32_t sBb   = sbase + 65536;
    const int tid  = threadIdx.x;
    const int lane = tid & 31;
    const int wid  = tid >> 5;
    const int warp_m = wid >> 2;
    const int warp_n = wid & 3;
    const int row0 = blockIdx.x * 128;

    const int mrow = tid >> 3;            // 0..31
    const int c8   = tid & 7;
    const uint32_t swc = (uint32_t)((c8 ^ (mrow & 7)) << 4);

    const __half* bcol[4];
    uint32_t stO[4];
#pragma unroll
    for (int i = 0; i < 4; i++) {
        const int m = mrow + 32 * i;
        bcol[i] = Bt + (size_t)m * 256 + c8 * 8;
        stO[i] = (uint32_t)(m * 128) + swc;
    }

    // ---- prologue
    if (GATHER) {
        // A gathered from fp32 query -> fp16 into resident smem (sync stores;
        // visible after the first mainloop __syncthreads)
        const float* Aq = (const float*)Ain;
#pragma unroll
        for (int i = 0; i < 4; i++) {
            const int m = mrow + 32 * i;
            const float* arow = Aq + (size_t)map_row(row0 + m) * CH + c8 * 8;
#pragma unroll
            for (int t = 0; t < 4; t++) {
                float4 v0 = *(const float4*)(arow + t * 64);
                float4 v1 = *(const float4*)(arow + t * 64 + 4);
                __half h8[8];
                *(__half2*)(h8)     = __floats2half2_rn(v0.x, v0.y);
                *(__half2*)(h8 + 2) = __floats2half2_rn(v0.z, v0.w);
                *(__half2*)(h8 + 4) = __floats2half2_rn(v1.x, v1.y);
                *(__half2*)(h8 + 6) = __floats2half2_rn(v1.z, v1.w);
                *(uint4*)((char*)smem + t * 16384 + stO[i]) = *(uint4*)h8;
            }
        }
    } else {
        const __half* Ah = (const __half*)Ain;
#pragma unroll
        for (int i = 0; i < 4; i++) {
            const int m = mrow + 32 * i;
            const __half* arow = Ah + (size_t)(row0 + m) * 256 + c8 * 8;
#pragma unroll
            for (int t = 0; t < 4; t++)
                CP_ASYNC16(sbase + t * 16384 + stO[i], arow + t * 64);
        }
    }
#pragma unroll
    for (int i = 0; i < 4; i++)
        CP_ASYNC16(sBb + stO[i], bcol[i]);               // stage 0 -> buf 0
    CP_COMMIT();
#pragma unroll
    for (int i = 0; i < 4; i++)
        CP_ASYNC16(sBb + 16384 + stO[i], bcol[i] + 64);  // stage 1 -> buf 1
    CP_COMMIT();

    const int rA  = warp_m * 64 + (lane & 15);
    const int hiA = lane >> 4;
    const int xA  = lane & 7;
    const int rB  = warp_n * 32 + ((lane >> 4) << 3) + (lane & 7);
    const int hiB = (lane >> 3) & 1;
    const int xB  = lane & 7;

    float acc[4][4][4];
#pragma unroll
    for (int i = 0; i < 4; i++)
#pragma unroll
        for (int j = 0; j < 4; j++)
#pragma unroll
            for (int e = 0; e < 4; e++) acc[i][j][e] = 0.f;

    constexpr int S = NX * 4;
#pragma unroll 4
    for (int s = 0; s < S; ++s) {
        CP_WAIT1();            // stage s resident (<=1 pending: stage s+1)
        __syncthreads();       // also publishes GATHER A-stores on s==0

        // prefetch stage s+2 into buf (s+2)%3
        const int sp = s + 2;
        if (sp < S) {
            const int nxp = sp >> 2, tp = sp & 3;
            const size_t off = (size_t)nxp * (128 * 256) + tp * 64;
            const uint32_t so = sBb + (uint32_t)(sp % 3) * 16384;
#pragma unroll
            for (int i = 0; i < 4; i++)
                CP_ASYNC16(so + stO[i], bcol[i] + off);
        }
        CP_COMMIT();

        // compute: A slab (s&3), B buffer (s%3)
        const uint32_t sa = sbase + (uint32_t)(s & 3) * 16384;
        const uint32_t sb = sBb   + (uint32_t)(s % 3) * 16384;
#pragma unroll
        for (int kc = 0; kc < 4; kc++) {
            uint32_t af[4][4];
#pragma unroll
            for (int mt = 0; mt < 4; mt++) {
                const uint32_t addr = sa + (uint32_t)((rA + mt * 16) * 128)
                                    + (uint32_t)((((kc << 1) + hiA) ^ xA) << 4);
                LDMX4(af[mt][0], af[mt][1], af[mt][2], af[mt][3], addr);
            }
            uint32_t bf[4][2];
#pragma unroll
            for (int p = 0; p < 2; p++) {
                const uint32_t addr = sb + (uint32_t)((rB + p * 16) * 128)
                                    + (uint32_t)((((kc << 1) + hiB) ^ xB) << 4);
                LDMX4(bf[2*p][0], bf[2*p][1], bf[2*p+1][0], bf[2*p+1][1], addr);
            }
#pragma unroll
            for (int mt = 0; mt < 4; mt++)
#pragma unroll
                for (int nt = 0; nt < 4; nt++)
                    MMA_F16(acc[mt][nt], af[mt][0], af[mt][1], af[mt][2], af[mt][3],
                            bf[nt][0], bf[nt][1]);
        }

        // epilogue at end of each n-tile
        if ((s & 3) == 3) {
            const int col0 = (s >> 2) * 128;
            const int rbase = row0 + warp_m * 64 + (lane >> 2);
            const int cb0   = col0 + warp_n * 32 + 2 * (lane & 3);
#pragma unroll
            for (int nt = 0; nt < 4; nt++) {
                const int cc = cb0 + nt * 8;
                const float bv0 = bias[cc], bv1 = bias[cc + 1];
                const float post = (GATHER && cc < 256) ? QSCALE : 1.f;
#pragma unroll
                for (int mt = 0; mt < 4; mt++) {
                    const int r = rbase + mt * 16;
                    float v[4];
#pragma unroll
                    for (int e = 0; e < 4; e++) {
                        float x = acc[mt][nt][e] + ((e & 1) ? bv1 : bv0);
                        if (GELU) {
                            float x3 = x * x * x;
                            x = 0.5f * x * (1.f + tanh_fast(0.7978845608028654f * (x + 0.044715f * x3)));
                        }
                        v[e] = x * post;
                        acc[mt][nt][e] = 0.f;
                    }
                    *(__half2*)(C + (size_t)r * N + cc)       = __floats2half2_rn(v[0], v[1]);
                    *(__half2*)(C + (size_t)(r + 8) * N + cc) = __floats2half2_rn(v[2], v[3]);
                }
            }
        }
    }
}

// ---------------- fp16 mma.sync GEMM (frozen R8/R9) — used for mlp2 (K=768) ----
#define STAGE_BYTES 32768
#define NSTAGE      3
#define GEMM_SMEM   (NSTAGE * STAGE_BYTES)

__global__ __launch_bounds__(256, 2)
void gemm_mma(const __half* __restrict__ A, const __half* __restrict__ Bt,
              const float* __restrict__ bias, __half* __restrict__ C,
              int N, int Kd)
{
    extern __shared__ float smem[];
    const uint32_t sbase = smem_u32(smem);
    const int tid  = threadIdx.x;
    const int lane = tid & 31;
    const int wid  = tid >> 5;
    const int warp_m = wid >> 2;
    const int warp_n = wid & 3;
    const int row0 = blockIdx.y * 128;
    const int col0 = blockIdx.x * 128;

    const int mrow = tid >> 3;
    const int c8   = tid & 7;
    const uint32_t swc = (uint32_t)((c8 ^ (mrow & 7)) << 4);

    const __half* arow[4];
    const __half* brow[4];
    uint32_t stA[4];
#pragma unroll
    for (int i = 0; i < 4; i++) {
        const int m = mrow + 32 * i;
        arow[i] = A + (size_t)(row0 + m) * Kd + c8 * 8;
        brow[i] = Bt + (size_t)(col0 + m) * Kd + c8 * 8;
        stA[i] = (uint32_t)(m * 128) + swc;
    }

    const int rA  = warp_m * 64 + (lane & 15);
    const int hiA = lane >> 4;
    const int xA  = lane & 7;
    const int rB  = warp_n * 32 + ((lane >> 4) << 3) + (lane & 7);
    const int hiB = (lane >> 3) & 1;
    const int xB  = lane & 7;

    float acc[4][4][4];
#pragma unroll
    for (int i = 0; i < 4; i++)
#pragma unroll
        for (int j = 0; j < 4; j++)
#pragma unroll
            for (int e = 0; e < 4; e++) acc[i][j][e] = 0.f;

    const int T = Kd >> 6;

#pragma unroll
    for (int s = 0; s < NSTAGE - 1; s++) {
        const int k0 = s * 64;
        const uint32_t so = sbase + s * STAGE_BYTES;
#pragma unroll
        for (int i = 0; i < 4; i++) {
            CP_ASYNC16(so + stA[i],         arow[i] + k0);
            CP_ASYNC16(so + stA[i] + 16384, brow[i] + k0);
        }
        CP_COMMIT();
    }

    for (int t = 0; t < T; ++t) {
        CP_WAIT1();
        __syncthreads();

        const int kt = t + NSTAGE - 1;
        if (kt < T) {
            const int k0 = kt * 64;
            const uint32_t so = sbase + (kt % NSTAGE) * STAGE_BYTES;
#pragma unroll
            for (int i = 0; i < 4; i++) {
                CP_ASYNC16(so + stA[i],         arow[i] + k0);
                CP_ASYNC16(so + stA[i] + 16384, brow[i] + k0);
            }
        }
        CP_COMMIT();

        const uint32_t sa = sbase + (t % NSTAGE) * STAGE_BYTES;
        const uint32_t sb = sa + 16384;
#pragma unroll
        for (int kc = 0; kc < 4; kc++) {
            uint32_t af[4][4];
#pragma unroll
            for (int mt = 0; mt < 4; mt++) {
                const uint32_t addr = sa + (uint32_t)((rA + mt * 16) * 128)
                                    + (uint32_t)((((kc << 1) + hiA) ^ xA) << 4);
                LDMX4(af[mt][0], af[mt][1], af[mt][2], af[mt][3], addr);
            }
            uint32_t bf[4][2];
#pragma unroll
            for (int p = 0; p < 2; p++) {
                const uint32_t addr = sb + (uint32_t)((rB + p * 16) * 128)
                                    + (uint32_t)((((kc << 1) + hiB) ^ xB) << 4);
                LDMX4(bf[2*p][0], bf[2*p][1], bf[2*p+1][0], bf[2*p+1][1], addr);
            }
#pragma unroll
            for (int mt = 0; mt < 4; mt++)
#pragma unroll
                for (int nt = 0; nt < 4; nt++)
                    MMA_F16(acc[mt][nt], af[mt][0], af[mt][1], af[mt][2], af[mt][3],
                            bf[nt][0], bf[nt][1]);
        }
    }

    const int rbase = row0 + warp_m * 64 + (lane >> 2);
    const int cb0   = col0 + warp_n * 32 + 2 * (lane & 3);
#pragma unroll
    for (int nt = 0; nt < 4; nt++) {
        const int cc = cb0 + nt * 8;
        const float bv0 = bias[cc], bv1 = bias[cc + 1];
#pragma unroll
        for (int mt = 0; mt < 4; mt++) {
            const int r = rbase + mt * 16;
            float v[4];
#pragma unroll
            for (int e = 0; e < 4; e++)
                v[e] = acc[mt][nt][e] + ((e & 1) ? bv1 : bv0);
            *(__half2*)(C + (size_t)r * N + cc)       = __floats2half2_rn(v[0], v[1]);
            *(__half2*)(C + (size_t)(r + 8) * N + cc) = __floats2half2_rn(v[2], v[3]);
        }
    }
}

// ---------------- attention (frozen R10, fp16 bm) ------------------------------
#define AQ_STR 40
#define AV_STR 72

__global__ __launch_bounds__(128)
void attn_kernel(const __half* __restrict__ qkv, const __half* __restrict__ bm,
                 __half* __restrict__ o)
{
    const int w = blockIdx.x, head = blockIdx.y;
    const int tid = threadIdx.x;
    const int lane = tid & 31;
    const int wid  = tid >> 5;

    __shared__ __align__(16) __half sQ[64 * AQ_STR];
    __shared__ __align__(16) __half sK[64 * AQ_STR];
    __shared__ __align__(16) __half sVt[32 * AV_STR];

    {
        const int row  = tid >> 1;
        const int half16 = (tid & 1) * 16;
        const __half* base = qkv + (size_t)(w * 64 + row) * 768 + head * 32 + half16;
        uint4 qv0 = *(const uint4*)(base);
        uint4 qv1 = *(const uint4*)(base + 8);
        uint4 kv0 = *(const uint4*)(base + 256);
        uint4 kv1 = *(const uint4*)(base + 264);
        *(uint4*)(sQ + row * AQ_STR + half16)     = qv0;
        *(uint4*)(sQ + row * AQ_STR + half16 + 8) = qv1;
        *(uint4*)(sK + row * AQ_STR + half16)     = kv0;
        *(uint4*)(sK + row * AQ_STR + half16 + 8) = kv1;
        __half vv[16];
        *(uint4*)(vv)     = *(const uint4*)(base + 512);
        *(uint4*)(vv + 8) = *(const uint4*)(base + 520);
#pragma unroll
        for (int j = 0; j < 16; j++)
            sVt[(half16 + j) * AV_STR + row] = vv[j];
    }
    __syncthreads();

    const uint32_t sQb  = smem_u32(sQ);
    const uint32_t sKb  = smem_u32(sK);
    const uint32_t sVtb = smem_u32(sVt);

    const int rA  = (lane & 15);
    const int hiA = lane >> 4;
    const int rBl = ((lane >> 4) << 3) + (lane & 7);
    const int hiB = (lane >> 3) & 1;

    float acc[8][4];
#pragma unroll
    for (int nt = 0; nt < 8; nt++)
#pragma unroll
        for (int e = 0; e < 4; e++) acc[nt][e] = 0.f;

#pragma unroll
    for (int kc = 0; kc < 2; kc++) {
        uint32_t a0, a1, a2, a3;
        {
            const uint32_t addr = sQb + (uint32_t)(((wid * 16 + rA) * AQ_STR
                                   + kc * 16 + hiA * 8) * 2);
            LDMX4(a0, a1, a2, a3, addr);
        }
#pragma unroll
        for (int p = 0; p < 4; p++) {
            uint32_t b00, b01, b10, b11;
            const uint32_t addr = sKb + (uint32_t)(((p * 16 + rBl) * AQ_STR
                                   + kc * 16 + hiB * 8) * 2);
            LDMX4(b00, b01, b10, b11, addr);
            MMA_F16(acc[2*p],   a0, a1, a2, a3, b00, b01);
            MMA_F16(acc[2*p+1], a0, a1, a2, a3, b10, b11);
        }
    }

    const __half* bmr = bm + (size_t)((w & 63) * 8 + head) * 4096;
    const int r0 = wid * 16 + (lane >> 2);
    const int cb = 2 * (lane & 3);
#pragma unroll
    for (int nt = 0; nt < 8; nt++) {
        const float2 blo = __half22float2(*(const __half2*)(bmr + r0 * 64 + 8 * nt + cb));
        const float2 bhi = __half22float2(*(const __half2*)(bmr + (r0 + 8) * 64 + 8 * nt + cb));
        acc[nt][0] += blo.x; acc[nt][1] += blo.y;
        acc[nt][2] += bhi.x; acc[nt][3] += bhi.y;
    }
    float m0 = -1e30f, m1 = -1e30f;
#pragma unroll
    for (int nt = 0; nt < 8; nt++) {
        m0 = fmaxf(m0, fmaxf(acc[nt][0], acc[nt][1]));
        m1 = fmaxf(m1, fmaxf(acc[nt][2], acc[nt][3]));
    }
    m0 = fmaxf(m0, __shfl_xor_sync(0xffffffffu, m0, 1));
    m0 = fmaxf(m0, __shfl_xor_sync(0xffffffffu, m0, 2));
    m1 = fmaxf(m1, __shfl_xor_sync(0xffffffffu, m1, 1));
    m1 = fmaxf(m1, __shfl_xor_sync(0xffffffffu, m1, 2));

    float s0 = 0.f, s1 = 0.f;
#pragma unroll
    for (int nt = 0; nt < 8; nt++) {
        acc[nt][0] = __expf(acc[nt][0] - m0); s0 += acc[nt][0];
        acc[nt][1] = __expf(acc[nt][1] - m0); s0 += acc[nt][1];
        acc[nt][2] = __expf(acc[nt][2] - m1); s1 += acc[nt][2];
        acc[nt][3] = __expf(acc[nt][3] - m1); s1 += acc[nt][3];
    }
    s0 += __shfl_xor_sync(0xffffffffu, s0, 1);
    s0 += __shfl_xor_sync(0xffffffffu, s0, 2);
    s1 += __shfl_xor_sync(0xffffffffu, s1, 1);
    s1 += __shfl_xor_sync(0xffffffffu, s1, 2);
    const float inv0 = 1.f / s0, inv1 = 1.f / s1;

    float oacc[4][4];
#pragma unroll
    for (int nt = 0; nt < 4; nt++)
#pragma unroll
        for (int e = 0; e < 4; e++) oacc[nt][e] = 0.f;

#pragma unroll
    for (int kc = 0; kc < 4; kc++) {
        const uint32_t a0 = h2pack(acc[2*kc][0]   * inv0, acc[2*kc][1]   * inv0);
        const uint32_t a1 = h2pack(acc[2*kc][2]   * inv1, acc[2*kc][3]   * inv1);
        const uint32_t a2 = h2pack(acc[2*kc+1][0] * inv0, acc[2*kc+1][1] * inv0);
        const uint32_t a3 = h2pack(acc[2*kc+1][2] * inv1, acc[2*kc+1][3] * inv1);
#pragma unroll
        for (int p = 0; p < 2; p++) {
            uint32_t b00, b01, b10, b11;
            const uint32_t addr = sVtb + (uint32_t)(((p * 16 + rBl) * AV_STR
                                   + kc * 16 + hiB * 8) * 2);
            LDMX4(b00, b01, b10, b11, addr);
            MMA_F16(oacc[2*p],   a0, a1, a2, a3, b00, b01);
            MMA_F16(oacc[2*p+1], a0, a1, a2, a3, b10, b11);
        }
    }

    __half* obase = o + (size_t)(w * 64 + r0) * 256 + head * 32;
#pragma unroll
    for (int nt = 0; nt < 4; nt++) {
        *(__half2*)(obase + 8 * nt + cb) = __floats2half2_rn(oacc[nt][0], oacc[nt][1]);
        *(__half2*)(obase + 8 * 256 + 8 * nt + cb) = __floats2half2_rn(oacc[nt][2], oacc[nt][3]);
    }
}

// ---------------- LayerNorm: warp-per-row, fp16 inputs (frozen R10) ------------
__global__ __launch_bounds__(256)
void ln1_kernel(const __half* __restrict__ X, const float* __restrict__ g,
                const float* __restrict__ b, const float* __restrict__ query,
                __half* __restrict__ out)
{
    const int row  = blockIdx.x * 8 + (threadIdx.x >> 5);
    const int lane = threadIdx.x & 31;
    const int c0   = lane * 8;

    __half x8[8];
    *(uint4*)(x8) = *(const uint4*)(X + (size_t)row * CH + c0);
    float v[8];
#pragma unroll
    for (int i = 0; i < 8; i++) v[i] = __half2float(x8[i]);

    float s = 0.f, s2 = 0.f;
#pragma unroll
    for (int i = 0; i < 8; i++) { s += v[i]; s2 += v[i] * v[i]; }
#pragma unroll
    for (int off = 16; off; off >>= 1) {
        s  += __shfl_xor_sync(0xffffffffu, s,  off);
        s2 += __shfl_xor_sync(0xffffffffu, s2, off);
    }
    const float mean = s * (1.f / 256.f);
    const float rstd = rsqrtf(s2 * (1.f / 256.f) - mean * mean + 1e-5f);

    float gv[8], bv[8], qv[8];
    *(float4*)(gv)     = *(const float4*)(g + c0);
    *(float4*)(gv + 4) = *(const float4*)(g + c0 + 4);
    *(float4*)(bv)     = *(const float4*)(b + c0);
    *(float4*)(bv + 4) = *(const float4*)(b + c0 + 4);
    const float* qr = query + (size_t)map_row(row) * CH + c0;
    *(float4*)(qv)     = *(const float4*)(qr);
    *(float4*)(qv + 4) = *(const float4*)(qr + 4);

    __half h8[8];
#pragma unroll
    for (int i = 0; i < 8; i++)
        h8[i] = __float2half((v[i] - mean) * rstd * gv[i] + bv[i] + qv[i]);
    *(uint4*)(out + (size_t)row * CH + c0) = *(uint4*)h8;
}

__global__ __launch_bounds__(256)
void ln2_kernel(const __half* __restrict__ X, const float* __restrict__ g,
                const float* __restrict__ b, const __half* __restrict__ x2,
                float* __restrict__ out)
{
    const int row  = blockIdx.x * 8 + (threadIdx.x >> 5);
    const int lane = threadIdx.x & 31;
    const int c0   = lane * 8;

    __half x8[8];
    *(uint4*)(x8) = *(const uint4*)(X + (size_t)row * CH + c0);
    float v[8];
#pragma unroll
    for (int i = 0; i < 8; i++) v[i] = __half2float(x8[i]);

    float s = 0.f, s2 = 0.f;
#pragma unroll
    for (int i = 0; i < 8; i++) { s += v[i]; s2 += v[i] * v[i]; }
#pragma unroll
    for (int off = 16; off; off >>= 1) {
        s  += __shfl_xor_sync(0xffffffffu, s,  off);
        s2 += __shfl_xor_sync(0xffffffffu, s2, off);
    }
    const float mean = s * (1.f / 256.f);
    const float rstd = rsqrtf(s2 * (1.f / 256.f) - mean * mean + 1e-5f);

    float gv[8], bv[8];
    *(float4*)(gv)     = *(const float4*)(g + c0);
    *(float4*)(gv + 4) = *(const float4*)(g + c0 + 4);
    *(float4*)(bv)     = *(const float4*)(b + c0);
    *(float4*)(bv + 4) = *(const float4*)(b + c0 + 4);
    __half r8[8];
    *(uint4*)(r8) = *(const uint4*)(x2 + (size_t)row * CH + c0);

    float o8[8];
#pragma unroll
    for (int i = 0; i < 8; i++)
        o8[i] = (v[i] - mean) * rstd * gv[i] + bv[i] + __half2float(r8[i]);
    float* op = out + (size_t)map_row(row) * CH + c0;
    *(float4*)(op)     = *(float4*)(o8);
    *(float4*)(op + 4) = *(float4*)(o8 + 4);
}

// ---------------- weight prep ----------------------------------------------------
__global__ __launch_bounds__(256)
void prep_kernel(const float* __restrict__ wq, const float* __restrict__ wk,
                 const float* __restrict__ wv, const float* __restrict__ bq,
                 const float* __restrict__ bk, const float* __restrict__ bv,
                 const float* __restrict__ wo, const float* __restrict__ w1,
                 const float* __restrict__ w2,
                 __half* __restrict__ wqkvT, float* __restrict__ bqkv,
                 __half* __restrict__ woT, __half* __restrict__ w1T,
                 __half* __restrict__ w2T)
{
    int i = blockIdx.x * 256 + threadIdx.x;
    if (i < 196608) {
        int n = i >> 8, k = i & 255;
        float v = (n < 256) ? wq[k * 256 + n]
                : (n < 512) ? wk[k * 256 + (n - 256)]
                            : wv[k * 256 + (n - 512)];
        wqkvT[i] = __float2half(v);
    } else if (i < 262144) {
        int j = i - 196608; int n = j >> 8, k = j & 255;
        woT[j] = __float2half(wo[k * 256 + n]);
    } else if (i < 458752) {
        int j = i - 262144; int n = j >> 8, k = j & 255;
        w1T[j] = __float2half(w1[k * 768 + n]);
    } else if (i < 655360) {
        int j = i - 458752; int n = j / 768, k = j - n * 768;
        w2T[j] = __float2half(w2[k * 256 + n]);
    } else if (i < 656128) {
        int n = i - 655360;
        bqkv[n] = (n < 256) ? bq[n] : (n < 512) ? bk[n - 256] : bv[n - 512];
    }
}

// ---------------- bias+mask table (fp16, mask clamped to -3e4) -------------------
__global__ __launch_bounds__(256)
void prep_bm_kernel(const float* __restrict__ rpe, const float* __restrict__ mask,
                    const int* __restrict__ rel, __half* __restrict__ bm)
{
    int idx = blockIdx.x * 256 + threadIdx.x;
    int wi  = idx >> 15;
    int rem = idx & 32767;
    int h   = rem >> 12;
    int ts  = rem & 4095;
    bm[idx] = __float2half(rpe[rel[ts] * NHEAD + h] + fmaxf(mask[wi * 4096 + ts], -30000.f));
}

// ---------------- launch ----------------------------------------------------------
extern "C" void kernel_launch(void* const* d_in, const int* in_sizes, int n_in,
                              void* d_out, int out_size)
{
    const float* query = (const float*)d_in[0];
    const float* wq = (const float*)d_in[1];  const float* bq = (const float*)d_in[2];
    const float* wk = (const float*)d_in[3];  const float* bk = (const float*)d_in[4];
    const float* wv = (const float*)d_in[5];  const float* bv = (const float*)d_in[6];
    const float* wo = (const float*)d_in[7];  const float* bo = (const float*)d_in[8];
    const float* rpe = (const float*)d_in[9];
    const float* ln1g = (const float*)d_in[10]; const float* ln1b = (const float*)d_in[11];
    const float* ln2g = (const float*)d_in[12]; const float* ln2b = (const float*)d_in[13];
    const float* w1 = (const float*)d_in[14]; const float* b1 = (const float*)d_in[15];
    const float* w2 = (const float*)d_in[16]; const float* b2 = (const float*)d_in[17];
    const float* amask = (const float*)d_in[18];
    const int*   rel   = (const int*)d_in[19];
    float* out = (float*)d_out;

    float *qkvf, *hf, *bqkv;
    __half *oh, *x2h, *wqkvT, *woT, *w1T, *w2T, *bm;
    cudaGetSymbolAddress((void**)&qkvf,  g_qkv);
    cudaGetSymbolAddress((void**)&hf,    g_h);
    cudaGetSymbolAddress((void**)&oh,    g_oh);
    cudaGetSymbolAddress((void**)&x2h,   g_x2h);
    cudaGetSymbolAddress((void**)&wqkvT, g_wqkvT);
    cudaGetSymbolAddress((void**)&bqkv,  g_bqkv);
    cudaGetSymbolAddress((void**)&woT,   g_woT);
    cudaGetSymbolAddress((void**)&w1T,   g_w1T);
    cudaGetSymbolAddress((void**)&w2T,   g_w2T);
    cudaGetSymbolAddress((void**)&bm,    g_bm);
    __half* qkvh = (__half*)qkvf;   // fp16 qkv / mlp1 alias
    __half* hh   = (__half*)hf;     // fp16 proj-out alias

    cudaFuncSetAttribute(gemm_nres<true,  false, 6>, cudaFuncAttributeMaxDynamicSharedMemorySize, NRES_SMEM);
    cudaFuncSetAttribute(gemm_nres<false, false, 2>, cudaFuncAttributeMaxDynamicSharedMemorySize, NRES_SMEM);
    cudaFuncSetAttribute(gemm_nres<false, true,  6>, cudaFuncAttributeMaxDynamicSharedMemorySize, NRES_SMEM);
    cudaFuncSetAttribute(gemm_mma, cudaFuncAttributeMaxDynamicSharedMemorySize, GEMM_SMEM);

    // prep: weights->fp16, bias/mask table (fp16)
    prep_kernel<<<2563, 256>>>(wq, wk, wv, bq, bk, bv, wo, w1, w2,
                               wqkvT, bqkv, woT, w1T, w2T);
    prep_bm_kernel<<<8192, 256>>>(rpe, amask, rel, bm);

    // fused QKV projection (A gathered+converted from fp32 query in-prologue)
    gemm_nres<true,  false, 6><<<1024, 256, NRES_SMEM>>>(query, wqkvT, bqkv, qkvh);

    // windowed attention -> fp16 oh
    attn_kernel<<<dim3(TOTW, NHEAD), 128>>>(qkvh, bm, oh);

    // output projection (A-resident) -> fp16 hh
    gemm_nres<false, false, 2><<<1024, 256, NRES_SMEM>>>(oh, woT, bo, hh);

    // LN1 + residual -> fp16 x2
    ln1_kernel<<<MROWS / 8, 256>>>(hh, ln1g, ln1b, query, x2h);

    // MLP: gelu(x2@w1+b1) -> fp16 (A-resident); @w2+b2 (K=768) -> fp16 oh
    gemm_nres<false, true,  6><<<1024, 256, NRES_SMEM>>>(x2h, w1T, b1, qkvh);
    gemm_mma<<<dim3(2, 1024), 256, GEMM_SMEM>>>(qkvh, w2T, b2, oh, 256, 768);

    // LN2 + residual, scatter to output
    ln2_kernel<<<MROWS / 8, 256>>>(oh, ln2g, ln2b, x2h, out);
}

// round 15
// speedup vs baseline: 1.0887x; 1.0080x over previous
#include <cuda_runtime.h>
#include <cuda_fp16.h>
#include <math.h>
#include <stdint.h>

#define BATCH 32
#define CH    256
#define EMB   256
#define NHEAD 8
#define SHFT  4
#define TT    64
#define TOTW  2048
#define MROWS 131072
#define HID   768

// ---------------- scratch ----------------
__device__ float  g_qkv[(size_t)MROWS * 768];   // fp16 alias: qkv out; later mlp1 out
__device__ float  g_h  [(size_t)MROWS * 256];   // fp16 alias: proj out
__device__ __half g_oh [(size_t)MROWS * 256];   // attn out; later mlp2 out (fp16)
__device__ __half g_x2h[(size_t)MROWS * 256];   // ln1 out / residual (fp16)
__device__ __half g_wqkvT[768 * 256];
__device__ float  g_bqkv [768];
__device__ __half g_woT  [256 * 256];
__device__ __half g_w1T  [768 * 256];
__device__ __half g_w2T  [256 * 768];
__device__ __half g_bm   [64 * 8 * 64 * 64];    // fp16 bias+mask [win][head][t][s]

// row (window*64+token) -> pixel index in original query (folds roll by -S)
__device__ __forceinline__ int map_row(int row) {
    int w  = row >> 6;
    int t  = row & 63;
    int b  = w >> 6;
    int wi = w & 63;
    int hb = wi >> 3, wb = wi & 7;
    int i  = ((hb << 3) + (t >> 3) + SHFT) & 63;
    int j  = ((wb << 3) + (t & 7) + SHFT) & 63;
    return (b << 12) + (i << 6) + j;
}

__device__ __forceinline__ uint32_t smem_u32(const void* p) {
    uint32_t a;
    asm("{ .reg .u64 t; cvta.to.shared.u64 t, %1; cvt.u32.u64 %0, t; }" : "=r"(a) : "l"(p));
    return a;
}

__device__ __forceinline__ float tanh_fast(float x) {
    float r;
    asm("tanh.approx.f32 %0, %1;" : "=f"(r) : "f"(x));
    return r;
}

__device__ __forceinline__ uint32_t h2pack(float lo, float hi) {
    __half2 h = __floats2half2_rn(lo, hi);
    return *(uint32_t*)&h;
}

#define LDMX4(r0, r1, r2, r3, addr) \
    asm volatile("ldmatrix.sync.aligned.m8n8.x4.shared.b16 {%0,%1,%2,%3}, [%4];" \
        : "=r"(r0), "=r"(r1), "=r"(r2), "=r"(r3) : "r"(addr))

#define LDMX4T(r0, r1, r2, r3, addr) \
    asm volatile("ldmatrix.sync.aligned.m8n8.x4.trans.shared.b16 {%0,%1,%2,%3}, [%4];" \
        : "=r"(r0), "=r"(r1), "=r"(r2), "=r"(r3) : "r"(addr))

#define MMA_F16(d, a0, a1, a2, a3, b0, b1) \
    asm volatile("mma.sync.aligned.m16n8k16.row.col.f32.f16.f16.f32 " \
        "{%0,%1,%2,%3}, {%4,%5,%6,%7}, {%8,%9}, {%0,%1,%2,%3};" \
        : "+f"((d)[0]), "+f"((d)[1]), "+f"((d)[2]), "+f"((d)[3]) \
        : "r"(a0), "r"(a1), "r"(a2), "r"(a3), "r"(b0), "r"(b1))

#define CP_ASYNC16(dst, src) \
    asm volatile("cp.async.cg.shared.global [%0], [%1], 16;" :: "r"(dst), "l"(src))
#define CP_COMMIT()  asm volatile("cp.async.commit_group;" ::: "memory")
#define CP_WAIT1()   asm volatile("cp.async.wait_group 1;" ::: "memory")

#define QSCALE 0.17677669529663687f

// ================================================================================
// A-resident N-looped GEMM (K = 256 fixed) — frozen R14 config.
// ================================================================================
#define NRES_SMEM (65536 + 3 * 16384)

template<bool GATHER, bool GELU, int NX>
__global__ __launch_bounds__(256, 2)
void gemm_nres(const void* __restrict__ Ain, const __half* __restrict__ Bt,
               const float* __restrict__ bias, __half* __restrict__ C)
{
    constexpr int N = NX * 128;
    extern __shared__ float smem[];
    const uint32_t sbase = smem_u32(smem);
    const uint32_t sBb   = sbase + 65536;
    const int tid  = threadIdx.x;
    const int lane = tid & 31;
    const int wid  = tid >> 5;
    const int warp_m = wid >> 2;
    const int warp_n = wid & 3;
    const int row0 = blockIdx.x * 128;

    const int mrow = tid >> 3;
    const int c8   = tid & 7;
    const uint32_t swc = (uint32_t)((c8 ^ (mrow & 7)) << 4);

    const __half* bcol[4];
    uint32_t stO[4];
#pragma unroll
    for (int i = 0; i < 4; i++) {
        const int m = mrow + 32 * i;
        bcol[i] = Bt + (size_t)m * 256 + c8 * 8;
        stO[i] = (uint32_t)(m * 128) + swc;
    }

    // ---- prologue
    if (GATHER) {
        const float* Aq = (const float*)Ain;
#pragma unroll
        for (int i = 0; i < 4; i++) {
            const int m = mrow + 32 * i;
            const float* arow = Aq + (size_t)map_row(row0 + m) * CH + c8 * 8;
#pragma unroll
            for (int t = 0; t < 4; t++) {
                float4 v0 = *(const float4*)(arow + t * 64);
                float4 v1 = *(const float4*)(arow + t * 64 + 4);
                __half h8[8];
                *(__half2*)(h8)     = __floats2half2_rn(v0.x, v0.y);
                *(__half2*)(h8 + 2) = __floats2half2_rn(v0.z, v0.w);
                *(__half2*)(h8 + 4) = __floats2half2_rn(v1.x, v1.y);
                *(__half2*)(h8 + 6) = __floats2half2_rn(v1.z, v1.w);
                *(uint4*)((char*)smem + t * 16384 + stO[i]) = *(uint4*)h8;
            }
        }
    } else {
        const __half* Ah = (const __half*)Ain;
#pragma unroll
        for (int i = 0; i < 4; i++) {
            const int m = mrow + 32 * i;
            const __half* arow = Ah + (size_t)(row0 + m) * 256 + c8 * 8;
#pragma unroll
            for (int t = 0; t < 4; t++)
                CP_ASYNC16(sbase + t * 16384 + stO[i], arow + t * 64);
        }
    }
#pragma unroll
    for (int i = 0; i < 4; i++)
        CP_ASYNC16(sBb + stO[i], bcol[i]);
    CP_COMMIT();
#pragma unroll
    for (int i = 0; i < 4; i++)
        CP_ASYNC16(sBb + 16384 + stO[i], bcol[i] + 64);
    CP_COMMIT();

    const int rA  = warp_m * 64 + (lane & 15);
    const int hiA = lane >> 4;
    const int xA  = lane & 7;
    const int rB  = warp_n * 32 + ((lane >> 4) << 3) + (lane & 7);
    const int hiB = (lane >> 3) & 1;
    const int xB  = lane & 7;

    float acc[4][4][4];
#pragma unroll
    for (int i = 0; i < 4; i++)
#pragma unroll
        for (int j = 0; j < 4; j++)
#pragma unroll
            for (int e = 0; e < 4; e++) acc[i][j][e] = 0.f;

    constexpr int S = NX * 4;
#pragma unroll 4
    for (int s = 0; s < S; ++s) {
        CP_WAIT1();
        __syncthreads();

        const int sp = s + 2;
        if (sp < S) {
            const int nxp = sp >> 2, tp = sp & 3;
            const size_t off = (size_t)nxp * (128 * 256) + tp * 64;
            const uint32_t so = sBb + (uint32_t)(sp % 3) * 16384;
#pragma unroll
            for (int i = 0; i < 4; i++)
                CP_ASYNC16(so + stO[i], bcol[i] + off);
        }
        CP_COMMIT();

        const uint32_t sa = sbase + (uint32_t)(s & 3) * 16384;
        const uint32_t sb = sBb   + (uint32_t)(s % 3) * 16384;
#pragma unroll
        for (int kc = 0; kc < 4; kc++) {
            uint32_t af[4][4];
#pragma unroll
            for (int mt = 0; mt < 4; mt++) {
                const uint32_t addr = sa + (uint32_t)((rA + mt * 16) * 128)
                                    + (uint32_t)((((kc << 1) + hiA) ^ xA) << 4);
                LDMX4(af[mt][0], af[mt][1], af[mt][2], af[mt][3], addr);
            }
            uint32_t bf[4][2];
#pragma unroll
            for (int p = 0; p < 2; p++) {
                const uint32_t addr = sb + (uint32_t)((rB + p * 16) * 128)
                                    + (uint32_t)((((kc << 1) + hiB) ^ xB) << 4);
                LDMX4(bf[2*p][0], bf[2*p][1], bf[2*p+1][0], bf[2*p+1][1], addr);
            }
#pragma unroll
            for (int mt = 0; mt < 4; mt++)
#pragma unroll
                for (int nt = 0; nt < 4; nt++)
                    MMA_F16(acc[mt][nt], af[mt][0], af[mt][1], af[mt][2], af[mt][3],
                            bf[nt][0], bf[nt][1]);
        }

        if ((s & 3) == 3) {
            const int col0 = (s >> 2) * 128;
            const int rbase = row0 + warp_m * 64 + (lane >> 2);
            const int cb0   = col0 + warp_n * 32 + 2 * (lane & 3);
#pragma unroll
            for (int nt = 0; nt < 4; nt++) {
                const int cc = cb0 + nt * 8;
                const float bv0 = bias[cc], bv1 = bias[cc + 1];
                const float post = (GATHER && cc < 256) ? QSCALE : 1.f;
#pragma unroll
                for (int mt = 0; mt < 4; mt++) {
                    const int r = rbase + mt * 16;
                    float v[4];
#pragma unroll
                    for (int e = 0; e < 4; e++) {
                        float x = acc[mt][nt][e] + ((e & 1) ? bv1 : bv0);
                        if (GELU) {
                            float x3 = x * x * x;
                            x = 0.5f * x * (1.f + tanh_fast(0.7978845608028654f * (x + 0.044715f * x3)));
                        }
                        v[e] = x * post;
                        acc[mt][nt][e] = 0.f;
                    }
                    *(__half2*)(C + (size_t)r * N + cc)       = __floats2half2_rn(v[0], v[1]);
                    *(__half2*)(C + (size_t)(r + 8) * N + cc) = __floats2half2_rn(v[2], v[3]);
                }
            }
        }
    }
}

// ---------------- fp16 mma.sync GEMM (frozen) — used for mlp2 (K=768) ----------
#define STAGE_BYTES 32768
#define NSTAGE      3
#define GEMM_SMEM   (NSTAGE * STAGE_BYTES)

__global__ __launch_bounds__(256, 2)
void gemm_mma(const __half* __restrict__ A, const __half* __restrict__ Bt,
              const float* __restrict__ bias, __half* __restrict__ C,
              int N, int Kd)
{
    extern __shared__ float smem[];
    const uint32_t sbase = smem_u32(smem);
    const int tid  = threadIdx.x;
    const int lane = tid & 31;
    const int wid  = tid >> 5;
    const int warp_m = wid >> 2;
    const int warp_n = wid & 3;
    const int row0 = blockIdx.y * 128;
    const int col0 = blockIdx.x * 128;

    const int mrow = tid >> 3;
    const int c8   = tid & 7;
    const uint32_t swc = (uint32_t)((c8 ^ (mrow & 7)) << 4);

    const __half* arow[4];
    const __half* brow[4];
    uint32_t stA[4];
#pragma unroll
    for (int i = 0; i < 4; i++) {
        const int m = mrow + 32 * i;
        arow[i] = A + (size_t)(row0 + m) * Kd + c8 * 8;
        brow[i] = Bt + (size_t)(col0 + m) * Kd + c8 * 8;
        stA[i] = (uint32_t)(m * 128) + swc;
    }

    const int rA  = warp_m * 64 + (lane & 15);
    const int hiA = lane >> 4;
    const int xA  = lane & 7;
    const int rB  = warp_n * 32 + ((lane >> 4) << 3) + (lane & 7);
    const int hiB = (lane >> 3) & 1;
    const int xB  = lane & 7;

    float acc[4][4][4];
#pragma unroll
    for (int i = 0; i < 4; i++)
#pragma unroll
        for (int j = 0; j < 4; j++)
#pragma unroll
            for (int e = 0; e < 4; e++) acc[i][j][e] = 0.f;

    const int T = Kd >> 6;

#pragma unroll
    for (int s = 0; s < NSTAGE - 1; s++) {
        const int k0 = s * 64;
        const uint32_t so = sbase + s * STAGE_BYTES;
#pragma unroll
        for (int i = 0; i < 4; i++) {
            CP_ASYNC16(so + stA[i],         arow[i] + k0);
            CP_ASYNC16(so + stA[i] + 16384, brow[i] + k0);
        }
        CP_COMMIT();
    }

    for (int t = 0; t < T; ++t) {
        CP_WAIT1();
        __syncthreads();

        const int kt = t + NSTAGE - 1;
        if (kt < T) {
            const int k0 = kt * 64;
            const uint32_t so = sbase + (kt % NSTAGE) * STAGE_BYTES;
#pragma unroll
            for (int i = 0; i < 4; i++) {
                CP_ASYNC16(so + stA[i],         arow[i] + k0);
                CP_ASYNC16(so + stA[i] + 16384, brow[i] + k0);
            }
        }
        CP_COMMIT();

        const uint32_t sa = sbase + (t % NSTAGE) * STAGE_BYTES;
        const uint32_t sb = sa + 16384;
#pragma unroll
        for (int kc = 0; kc < 4; kc++) {
            uint32_t af[4][4];
#pragma unroll
            for (int mt = 0; mt < 4; mt++) {
                const uint32_t addr = sa + (uint32_t)((rA + mt * 16) * 128)
                                    + (uint32_t)((((kc << 1) + hiA) ^ xA) << 4);
                LDMX4(af[mt][0], af[mt][1], af[mt][2], af[mt][3], addr);
            }
            uint32_t bf[4][2];
#pragma unroll
            for (int p = 0; p < 2; p++) {
                const uint32_t addr = sb + (uint32_t)((rB + p * 16) * 128)
                                    + (uint32_t)((((kc << 1) + hiB) ^ xB) << 4);
                LDMX4(bf[2*p][0], bf[2*p][1], bf[2*p+1][0], bf[2*p+1][1], addr);
            }
#pragma unroll
            for (int mt = 0; mt < 4; mt++)
#pragma unroll
                for (int nt = 0; nt < 4; nt++)
                    MMA_F16(acc[mt][nt], af[mt][0], af[mt][1], af[mt][2], af[mt][3],
                            bf[nt][0], bf[nt][1]);
        }
    }

    const int rbase = row0 + warp_m * 64 + (lane >> 2);
    const int cb0   = col0 + warp_n * 32 + 2 * (lane & 3);
#pragma unroll
    for (int nt = 0; nt < 4; nt++) {
        const int cc = cb0 + nt * 8;
        const float bv0 = bias[cc], bv1 = bias[cc + 1];
#pragma unroll
        for (int mt = 0; mt < 4; mt++) {
            const int r = rbase + mt * 16;
            float v[4];
#pragma unroll
            for (int e = 0; e < 4; e++)
                v[e] = acc[mt][nt][e] + ((e & 1) ? bv1 : bv0);
            *(__half2*)(C + (size_t)r * N + cc)       = __floats2half2_rn(v[0], v[1]);
            *(__half2*)(C + (size_t)(r + 8) * N + cc) = __floats2half2_rn(v[2], v[3]);
        }
    }
}

// ---------------- attention v7: trans-ldmatrix V, bm preloaded into acc --------
#define AQ_STR 40

__global__ __launch_bounds__(128)
void attn_kernel(const __half* __restrict__ qkv, const __half* __restrict__ bm,
                 __half* __restrict__ o)
{
    const int w = blockIdx.x, head = blockIdx.y;
    const int tid = threadIdx.x;
    const int lane = tid & 31;
    const int wid  = tid >> 5;

    __shared__ __align__(16) __half sQ[64 * AQ_STR];
    __shared__ __align__(16) __half sK[64 * AQ_STR];
    __shared__ __align__(16) __half sV[64 * AQ_STR];   // row-major [s][d]

    {
        const int row  = tid >> 1;
        const int half16 = (tid & 1) * 16;
        const __half* base = qkv + (size_t)(w * 64 + row) * 768 + head * 32 + half16;
        uint4 qv0 = *(const uint4*)(base);
        uint4 qv1 = *(const uint4*)(base + 8);
        uint4 kv0 = *(const uint4*)(base + 256);
        uint4 kv1 = *(const uint4*)(base + 264);
        uint4 vv0 = *(const uint4*)(base + 512);
        uint4 vv1 = *(const uint4*)(base + 520);
        *(uint4*)(sQ + row * AQ_STR + half16)     = qv0;
        *(uint4*)(sQ + row * AQ_STR + half16 + 8) = qv1;
        *(uint4*)(sK + row * AQ_STR + half16)     = kv0;
        *(uint4*)(sK + row * AQ_STR + half16 + 8) = kv1;
        *(uint4*)(sV + row * AQ_STR + half16)     = vv0;
        *(uint4*)(sV + row * AQ_STR + half16 + 8) = vv1;
    }

    // preload bias+mask into accumulators (fp32) while smem fills
    const __half* bmr = bm + (size_t)((w & 63) * 8 + head) * 4096;
    const int r0 = wid * 16 + (lane >> 2);
    const int cb = 2 * (lane & 3);
    float acc[8][4];
#pragma unroll
    for (int nt = 0; nt < 8; nt++) {
        const float2 blo = __half22float2(*(const __half2*)(bmr + r0 * 64 + 8 * nt + cb));
        const float2 bhi = __half22float2(*(const __half2*)(bmr + (r0 + 8) * 64 + 8 * nt + cb));
        acc[nt][0] = blo.x; acc[nt][1] = blo.y;
        acc[nt][2] = bhi.x; acc[nt][3] = bhi.y;
    }
    __syncthreads();

    const uint32_t sQb = smem_u32(sQ);
    const uint32_t sKb = smem_u32(sK);
    const uint32_t sVb = smem_u32(sV);

    const int rA  = (lane & 15);
    const int hiA = lane >> 4;
    const int rBl = ((lane >> 4) << 3) + (lane & 7);
    const int hiB = (lane >> 3) & 1;
    // trans-ldmatrix lane mapping (B from K-major rows)
    const int rowS = ((lane >> 3) & 1) * 8 + (lane & 7);   // s within 16-row block
    const int colD = (lane >> 4) * 8;                      // d 8-col half

    // ---- QK^T (k=32 -> 2 kc of k16), acc pre-seeded with bias+mask
#pragma unroll
    for (int kc = 0; kc < 2; kc++) {
        uint32_t a0, a1, a2, a3;
        {
            const uint32_t addr = sQb + (uint32_t)(((wid * 16 + rA) * AQ_STR
                                   + kc * 16 + hiA * 8) * 2);
            LDMX4(a0, a1, a2, a3, addr);
        }
#pragma unroll
        for (int p = 0; p < 4; p++) {
            uint32_t b00, b01, b10, b11;
            const uint32_t addr = sKb + (uint32_t)(((p * 16 + rBl) * AQ_STR
                                   + kc * 16 + hiB * 8) * 2);
            LDMX4(b00, b01, b10, b11, addr);
            MMA_F16(acc[2*p],   a0, a1, a2, a3, b00, b01);
            MMA_F16(acc[2*p+1], a0, a1, a2, a3, b10, b11);
        }
    }

    // ---- softmax on fragments (fp32)
    float m0 = -1e30f, m1 = -1e30f;
#pragma unroll
    for (int nt = 0; nt < 8; nt++) {
        m0 = fmaxf(m0, fmaxf(acc[nt][0], acc[nt][1]));
        m1 = fmaxf(m1, fmaxf(acc[nt][2], acc[nt][3]));
    }
    m0 = fmaxf(m0, __shfl_xor_sync(0xffffffffu, m0, 1));
    m0 = fmaxf(m0, __shfl_xor_sync(0xffffffffu, m0, 2));
    m1 = fmaxf(m1, __shfl_xor_sync(0xffffffffu, m1, 1));
    m1 = fmaxf(m1, __shfl_xor_sync(0xffffffffu, m1, 2));

    float s0 = 0.f, s1 = 0.f;
#pragma unroll
    for (int nt = 0; nt < 8; nt++) {
        acc[nt][0] = __expf(acc[nt][0] - m0); s0 += acc[nt][0];
        acc[nt][1] = __expf(acc[nt][1] - m0); s0 += acc[nt][1];
        acc[nt][2] = __expf(acc[nt][2] - m1); s1 += acc[nt][2];
        acc[nt][3] = __expf(acc[nt][3] - m1); s1 += acc[nt][3];
    }
    s0 += __shfl_xor_sync(0xffffffffu, s0, 1);
    s0 += __shfl_xor_sync(0xffffffffu, s0, 2);
    s1 += __shfl_xor_sync(0xffffffffu, s1, 1);
    s1 += __shfl_xor_sync(0xffffffffu, s1, 2);
    const float inv0 = 1.f / s0, inv1 = 1.f / s1;

    // ---- P @ V: P fragments in registers, V via trans-ldmatrix (row-major)
    float oacc[4][4];
#pragma unroll
    for (int nt = 0; nt < 4; nt++)
#pragma unroll
        for (int e = 0; e < 4; e++) oacc[nt][e] = 0.f;

#pragma unroll
    for (int kc = 0; kc < 4; kc++) {
        const uint32_t a0 = h2pack(acc[2*kc][0]   * inv0, acc[2*kc][1]   * inv0);
        const uint32_t a1 = h2pack(acc[2*kc][2]   * inv1, acc[2*kc][3]   * inv1);
        const uint32_t a2 = h2pack(acc[2*kc+1][0] * inv0, acc[2*kc+1][1] * inv0);
        const uint32_t a3 = h2pack(acc[2*kc+1][2] * inv1, acc[2*kc+1][3] * inv1);
#pragma unroll
        for (int p = 0; p < 2; p++) {
            uint32_t b00, b01, b10, b11;
            // rows = s (K-major), cols = d; .trans yields B fragments directly
            const uint32_t addr = sVb + (uint32_t)(((kc * 16 + rowS) * AQ_STR
                                   + p * 16 + colD) * 2);
            LDMX4T(b00, b01, b10, b11, addr);
            MMA_F16(oacc[2*p],   a0, a1, a2, a3, b00, b01);
            MMA_F16(oacc[2*p+1], a0, a1, a2, a3, b10, b11);
        }
    }

    __half* obase = o + (size_t)(w * 64 + r0) * 256 + head * 32;
#pragma unroll
    for (int nt = 0; nt < 4; nt++) {
        *(__half2*)(obase + 8 * nt + cb) = __floats2half2_rn(oacc[nt][0], oacc[nt][1]);
        *(__half2*)(obase + 8 * 256 + 8 * nt + cb) = __floats2half2_rn(oacc[nt][2], oacc[nt][3]);
    }
}

// ---------------- LayerNorm: warp-per-row, fp16 inputs (frozen R10) ------------
__global__ __launch_bounds__(256)
void ln1_kernel(const __half* __restrict__ X, const float* __restrict__ g,
                const float* __restrict__ b, const float* __restrict__ query,
                __half* __restrict__ out)
{
    const int row  = blockIdx.x * 8 + (threadIdx.x >> 5);
    const int lane = threadIdx.x & 31;
    const int c0   = lane * 8;

    __half x8[8];
    *(uint4*)(x8) = *(const uint4*)(X + (size_t)row * CH + c0);
    float v[8];
#pragma unroll
    for (int i = 0; i < 8; i++) v[i] = __half2float(x8[i]);

    float s = 0.f, s2 = 0.f;
#pragma unroll
    for (int i = 0; i < 8; i++) { s += v[i]; s2 += v[i] * v[i]; }
#pragma unroll
    for (int off = 16; off; off >>= 1) {
        s  += __shfl_xor_sync(0xffffffffu, s,  off);
        s2 += __shfl_xor_sync(0xffffffffu, s2, off);
    }
    const float mean = s * (1.f / 256.f);
    const float rstd = rsqrtf(s2 * (1.f / 256.f) - mean * mean + 1e-5f);

    float gv[8], bv[8], qv[8];
    *(float4*)(gv)     = *(const float4*)(g + c0);
    *(float4*)(gv + 4) = *(const float4*)(g + c0 + 4);
    *(float4*)(bv)     = *(const float4*)(b + c0);
    *(float4*)(bv + 4) = *(const float4*)(b + c0 + 4);
    const float* qr = query + (size_t)map_row(row) * CH + c0;
    *(float4*)(qv)     = *(const float4*)(qr);
    *(float4*)(qv + 4) = *(const float4*)(qr + 4);

    __half h8[8];
#pragma unroll
    for (int i = 0; i < 8; i++)
        h8[i] = __float2half((v[i] - mean) * rstd * gv[i] + bv[i] + qv[i]);
    *(uint4*)(out + (size_t)row * CH + c0) = *(uint4*)h8;
}

__global__ __launch_bounds__(256)
void ln2_kernel(const __half* __restrict__ X, const float* __restrict__ g,
                const float* __restrict__ b, const __half* __restrict__ x2,
                float* __restrict__ out)
{
    const int row  = blockIdx.x * 8 + (threadIdx.x >> 5);
    const int lane = threadIdx.x & 31;
    const int c0   = lane * 8;

    __half x8[8];
    *(uint4*)(x8) = *(const uint4*)(X + (size_t)row * CH + c0);
    float v[8];
#pragma unroll
    for (int i = 0; i < 8; i++) v[i] = __half2float(x8[i]);

    float s = 0.f, s2 = 0.f;
#pragma unroll
    for (int i = 0; i < 8; i++) { s += v[i]; s2 += v[i] * v[i]; }
#pragma unroll
    for (int off = 16; off; off >>= 1) {
        s  += __shfl_xor_sync(0xffffffffu, s,  off);
        s2 += __shfl_xor_sync(0xffffffffu, s2, off);
    }
    const float mean = s * (1.f / 256.f);
    const float rstd = rsqrtf(s2 * (1.f / 256.f) - mean * mean + 1e-5f);

    float gv[8], bv[8];
    *(float4*)(gv)     = *(const float4*)(g + c0);
    *(float4*)(gv + 4) = *(const float4*)(g + c0 + 4);
    *(float4*)(bv)     = *(const float4*)(b + c0);
    *(float4*)(bv + 4) = *(const float4*)(b + c0 + 4);
    __half r8[8];
    *(uint4*)(r8) = *(const uint4*)(x2 + (size_t)row * CH + c0);

    float o8[8];
#pragma unroll
    for (int i = 0; i < 8; i++)
        o8[i] = (v[i] - mean) * rstd * gv[i] + bv[i] + __half2float(r8[i]);
    float* op = out + (size_t)map_row(row) * CH + c0;
    *(float4*)(op)     = *(float4*)(o8);
    *(float4*)(op + 4) = *(float4*)(o8 + 4);
}

// ---------------- weight prep ----------------------------------------------------
__global__ __launch_bounds__(256)
void prep_kernel(const float* __restrict__ wq, const float* __restrict__ wk,
                 const float* __restrict__ wv, const float* __restrict__ bq,
                 const float* __restrict__ bk, const float* __restrict__ bv,
                 const float* __restrict__ wo, const float* __restrict__ w1,
                 const float* __restrict__ w2,
                 __half* __restrict__ wqkvT, float* __restrict__ bqkv,
                 __half* __restrict__ woT, __half* __restrict__ w1T,
                 __half* __restrict__ w2T)
{
    int i = blockIdx.x * 256 + threadIdx.x;
    if (i < 196608) {
        int n = i >> 8, k = i & 255;
        float v = (n < 256) ? wq[k * 256 + n]
                : (n < 512) ? wk[k * 256 + (n - 256)]
                            : wv[k * 256 + (n - 512)];
        wqkvT[i] = __float2half(v);
    } else if (i < 262144) {
        int j = i - 196608; int n = j >> 8, k = j & 255;
        woT[j] = __float2half(wo[k * 256 + n]);
    } else if (i < 458752) {
        int j = i - 262144; int n = j >> 8, k = j & 255;
        w1T[j] = __float2half(w1[k * 768 + n]);
    } else if (i < 655360) {
        int j = i - 458752; int n = j / 768, k = j - n * 768;
        w2T[j] = __float2half(w2[k * 256 + n]);
    } else if (i < 656128) {
        int n = i - 655360;
        bqkv[n] = (n < 256) ? bq[n] : (n < 512) ? bk[n - 256] : bv[n - 512];
    }
}

// ---------------- bias+mask table (fp16, mask clamped to -3e4) -------------------
__global__ __launch_bounds__(256)
void prep_bm_kernel(const float* __restrict__ rpe, const float* __restrict__ mask,
                    const int* __restrict__ rel, __half* __restrict__ bm)
{
    int idx = blockIdx.x * 256 + threadIdx.x;
    int wi  = idx >> 15;
    int rem = idx & 32767;
    int h   = rem >> 12;
    int ts  = rem & 4095;
    bm[idx] = __float2half(rpe[rel[ts] * NHEAD + h] + fmaxf(mask[wi * 4096 + ts], -30000.f));
}

// ---------------- launch ----------------------------------------------------------
extern "C" void kernel_launch(void* const* d_in, const int* in_sizes, int n_in,
                              void* d_out, int out_size)
{
    const float* query = (const float*)d_in[0];
    const float* wq = (const float*)d_in[1];  const float* bq = (const float*)d_in[2];
    const float* wk = (const float*)d_in[3];  const float* bk = (const float*)d_in[4];
    const float* wv = (const float*)d_in[5];  const float* bv = (const float*)d_in[6];
    const float* wo = (const float*)d_in[7];  const float* bo = (const float*)d_in[8];
    const float* rpe = (const float*)d_in[9];
    const float* ln1g = (const float*)d_in[10]; const float* ln1b = (const float*)d_in[11];
    const float* ln2g = (const float*)d_in[12]; const float* ln2b = (const float*)d_in[13];
    const float* w1 = (const float*)d_in[14]; const float* b1 = (const float*)d_in[15];
    const float* w2 = (const float*)d_in[16]; const float* b2 = (const float*)d_in[17];
    const float* amask = (const float*)d_in[18];
    const int*   rel   = (const int*)d_in[19];
    float* out = (float*)d_out;

    float *qkvf, *hf, *bqkv;
    __half *oh, *x2h, *wqkvT, *woT, *w1T, *w2T, *bm;
    cudaGetSymbolAddress((void**)&qkvf,  g_qkv);
    cudaGetSymbolAddress((void**)&hf,    g_h);
    cudaGetSymbolAddress((void**)&oh,    g_oh);
    cudaGetSymbolAddress((void**)&x2h,   g_x2h);
    cudaGetSymbolAddress((void**)&wqkvT, g_wqkvT);
    cudaGetSymbolAddress((void**)&bqkv,  g_bqkv);
    cudaGetSymbolAddress((void**)&woT,   g_woT);
    cudaGetSymbolAddress((void**)&w1T,   g_w1T);
    cudaGetSymbolAddress((void**)&w2T,   g_w2T);
    cudaGetSymbolAddress((void**)&bm,    g_bm);
    __half* qkvh = (__half*)qkvf;   // fp16 qkv / mlp1 alias
    __half* hh   = (__half*)hf;     // fp16 proj-out alias

    cudaFuncSetAttribute(gemm_nres<true,  false, 6>, cudaFuncAttributeMaxDynamicSharedMemorySize, NRES_SMEM);
    cudaFuncSetAttribute(gemm_nres<false, false, 2>, cudaFuncAttributeMaxDynamicSharedMemorySize, NRES_SMEM);
    cudaFuncSetAttribute(gemm_nres<false, true,  6>, cudaFuncAttributeMaxDynamicSharedMemorySize, NRES_SMEM);
    cudaFuncSetAttribute(gemm_mma, cudaFuncAttributeMaxDynamicSharedMemorySize, GEMM_SMEM);

    // prep: weights->fp16, bias/mask table (fp16)
    prep_kernel<<<2563, 256>>>(wq, wk, wv, bq, bk, bv, wo, w1, w2,
                               wqkvT, bqkv, woT, w1T, w2T);
    prep_bm_kernel<<<8192, 256>>>(rpe, amask, rel, bm);

    // fused QKV projection (A gathered+converted from fp32 query in-prologue)
    gemm_nres<true,  false, 6><<<1024, 256, NRES_SMEM>>>(query, wqkvT, bqkv, qkvh);

    // windowed attention -> fp16 oh
    attn_kernel<<<dim3(TOTW, NHEAD), 128>>>(qkvh, bm, oh);

    // output projection (A-resident) -> fp16 hh
    gemm_nres<false, false, 2><<<1024, 256, NRES_SMEM>>>(oh, woT, bo, hh);

    // LN1 + residual -> fp16 x2
    ln1_kernel<<<MROWS / 8, 256>>>(hh, ln1g, ln1b, query, x2h);

    // MLP: gelu(x2@w1+b1) -> fp16 (A-resident); @w2+b2 (K=768) -> fp16 oh
    gemm_nres<false, true,  6><<<1024, 256, NRES_SMEM>>>(x2h, w1T, b1, qkvh);
    gemm_mma<<<dim3(2, 1024), 256, GEMM_SMEM>>>(qkvh, w2T, b2, oh, 256, 768);

    // LN2 + residual, scatter to output
    ln2_kernel<<<MROWS / 8, 256>>>(oh, ln2g, ln2b, x2h, out);
}

// round 16
// speedup vs baseline: 1.1224x; 1.0310x over previous
#include <cuda_runtime.h>
#include <cuda_fp16.h>
#include <math.h>
#include <stdint.h>

#define BATCH 32
#define CH    256
#define EMB   256
#define NHEAD 8
#define SHFT  4
#define TT    64
#define TOTW  2048
#define MROWS 131072
#define HID   768

// ---------------- scratch ----------------
__device__ float  g_qkv[(size_t)MROWS * 768];   // fp16 alias: qkv out; later mlp1 out
__device__ float  g_h  [(size_t)MROWS * 256];   // fp16 alias: proj out
__device__ __half g_oh [(size_t)MROWS * 256];   // attn out; later mlp2 out (fp16)
__device__ __half g_x2h[(size_t)MROWS * 256];   // ln1 out / residual (fp16)
__device__ __half g_wqkvT[768 * 256];
__device__ float  g_bqkv [768];
__device__ __half g_woT  [256 * 256];
__device__ __half g_w1T  [768 * 256];
__device__ __half g_w2T  [256 * 768];
__device__ __half g_bm   [64 * 8 * 64 * 64];    // fp16 bias+mask, FRAGMENT layout:
                                                // [wi][h][chunk 0..3][tid 0..127][8]

// row (window*64+token) -> pixel index in original query (folds roll by -S)
__device__ __forceinline__ int map_row(int row) {
    int w  = row >> 6;
    int t  = row & 63;
    int b  = w >> 6;
    int wi = w & 63;
    int hb = wi >> 3, wb = wi & 7;
    int i  = ((hb << 3) + (t >> 3) + SHFT) & 63;
    int j  = ((wb << 3) + (t & 7) + SHFT) & 63;
    return (b << 12) + (i << 6) + j;
}

__device__ __forceinline__ uint32_t smem_u32(const void* p) {
    uint32_t a;
    asm("{ .reg .u64 t; cvta.to.shared.u64 t, %1; cvt.u32.u64 %0, t; }" : "=r"(a) : "l"(p));
    return a;
}

__device__ __forceinline__ float tanh_fast(float x) {
    float r;
    asm("tanh.approx.f32 %0, %1;" : "=f"(r) : "f"(x));
    return r;
}

__device__ __forceinline__ uint32_t h2pack(float lo, float hi) {
    __half2 h = __floats2half2_rn(lo, hi);
    return *(uint32_t*)&h;
}

#define LDMX4(r0, r1, r2, r3, addr) \
    asm volatile("ldmatrix.sync.aligned.m8n8.x4.shared.b16 {%0,%1,%2,%3}, [%4];" \
        : "=r"(r0), "=r"(r1), "=r"(r2), "=r"(r3) : "r"(addr))

#define LDMX4T(r0, r1, r2, r3, addr) \
    asm volatile("ldmatrix.sync.aligned.m8n8.x4.trans.shared.b16 {%0,%1,%2,%3}, [%4];" \
        : "=r"(r0), "=r"(r1), "=r"(r2), "=r"(r3) : "r"(addr))

#define MMA_F16(d, a0, a1, a2, a3, b0, b1) \
    asm volatile("mma.sync.aligned.m16n8k16.row.col.f32.f16.f16.f32 " \
        "{%0,%1,%2,%3}, {%4,%5,%6,%7}, {%8,%9}, {%0,%1,%2,%3};" \
        : "+f"((d)[0]), "+f"((d)[1]), "+f"((d)[2]), "+f"((d)[3]) \
        : "r"(a0), "r"(a1), "r"(a2), "r"(a3), "r"(b0), "r"(b1))

#define CP_ASYNC16(dst, src) \
    asm volatile("cp.async.cg.shared.global [%0], [%1], 16;" :: "r"(dst), "l"(src))
#define CP_COMMIT()  asm volatile("cp.async.commit_group;" ::: "memory")
#define CP_WAIT1()   asm volatile("cp.async.wait_group 1;" ::: "memory")

#define QSCALE 0.17677669529663687f

// ================================================================================
// A-resident N-looped GEMM (K = 256 fixed) — frozen R14 config.
// ================================================================================
#define NRES_SMEM (65536 + 3 * 16384)

template<bool GATHER, bool GELU, int NX>
__global__ __launch_bounds__(256, 2)
void gemm_nres(const void* __restrict__ Ain, const __half* __restrict__ Bt,
               const float* __restrict__ bias, __half* __restrict__ C)
{
    constexpr int N = NX * 128;
    extern __shared__ float smem[];
    const uint32_t sbase = smem_u32(smem);
    const uint32_t sBb   = sbase + 65536;
    const int tid  = threadIdx.x;
    const int lane = tid & 31;
    const int wid  = tid >> 5;
    const int warp_m = wid >> 2;
    const int warp_n = wid & 3;
    const int row0 = blockIdx.x * 128;

    const int mrow = tid >> 3;
    const int c8   = tid & 7;
    const uint32_t swc = (uint32_t)((c8 ^ (mrow & 7)) << 4);

    const __half* bcol[4];
    uint32_t stO[4];
#pragma unroll
    for (int i = 0; i < 4; i++) {
        const int m = mrow + 32 * i;
        bcol[i] = Bt + (size_t)m * 256 + c8 * 8;
        stO[i] = (uint32_t)(m * 128) + swc;
    }

    // ---- prologue
    if (GATHER) {
        const float* Aq = (const float*)Ain;
#pragma unroll
        for (int i = 0; i < 4; i++) {
            const int m = mrow + 32 * i;
            const float* arow = Aq + (size_t)map_row(row0 + m) * CH + c8 * 8;
#pragma unroll
            for (int t = 0; t < 4; t++) {
                float4 v0 = *(const float4*)(arow + t * 64);
                float4 v1 = *(const float4*)(arow + t * 64 + 4);
                __half h8[8];
                *(__half2*)(h8)     = __floats2half2_rn(v0.x, v0.y);
                *(__half2*)(h8 + 2) = __floats2half2_rn(v0.z, v0.w);
                *(__half2*)(h8 + 4) = __floats2half2_rn(v1.x, v1.y);
                *(__half2*)(h8 + 6) = __floats2half2_rn(v1.z, v1.w);
                *(uint4*)((char*)smem + t * 16384 + stO[i]) = *(uint4*)h8;
            }
        }
    } else {
        const __half* Ah = (const __half*)Ain;
#pragma unroll
        for (int i = 0; i < 4; i++) {
            const int m = mrow + 32 * i;
            const __half* arow = Ah + (size_t)(row0 + m) * 256 + c8 * 8;
#pragma unroll
            for (int t = 0; t < 4; t++)
                CP_ASYNC16(sbase + t * 16384 + stO[i], arow + t * 64);
        }
    }
#pragma unroll
    for (int i = 0; i < 4; i++)
        CP_ASYNC16(sBb + stO[i], bcol[i]);
    CP_COMMIT();
#pragma unroll
    for (int i = 0; i < 4; i++)
        CP_ASYNC16(sBb + 16384 + stO[i], bcol[i] + 64);
    CP_COMMIT();

    const int rA  = warp_m * 64 + (lane & 15);
    const int hiA = lane >> 4;
    const int xA  = lane & 7;
    const int rB  = warp_n * 32 + ((lane >> 4) << 3) + (lane & 7);
    const int hiB = (lane >> 3) & 1;
    const int xB  = lane & 7;

    float acc[4][4][4];
#pragma unroll
    for (int i = 0; i < 4; i++)
#pragma unroll
        for (int j = 0; j < 4; j++)
#pragma unroll
            for (int e = 0; e < 4; e++) acc[i][j][e] = 0.f;

    constexpr int S = NX * 4;
#pragma unroll 4
    for (int s = 0; s < S; ++s) {
        CP_WAIT1();
        __syncthreads();

        const int sp = s + 2;
        if (sp < S) {
            const int nxp = sp >> 2, tp = sp & 3;
            const size_t off = (size_t)nxp * (128 * 256) + tp * 64;
            const uint32_t so = sBb + (uint32_t)(sp % 3) * 16384;
#pragma unroll
            for (int i = 0; i < 4; i++)
                CP_ASYNC16(so + stO[i], bcol[i] + off);
        }
        CP_COMMIT();

        const uint32_t sa = sbase + (uint32_t)(s & 3) * 16384;
        const uint32_t sb = sBb   + (uint32_t)(s % 3) * 16384;
#pragma unroll
        for (int kc = 0; kc < 4; kc++) {
            uint32_t af[4][4];
#pragma unroll
            for (int mt = 0; mt < 4; mt++) {
                const uint32_t addr = sa + (uint32_t)((rA + mt * 16) * 128)
                                    + (uint32_t)((((kc << 1) + hiA) ^ xA) << 4);
                LDMX4(af[mt][0], af[mt][1], af[mt][2], af[mt][3], addr);
            }
            uint32_t bf[4][2];
#pragma unroll
            for (int p = 0; p < 2; p++) {
                const uint32_t addr = sb + (uint32_t)((rB + p * 16) * 128)
                                    + (uint32_t)((((kc << 1) + hiB) ^ xB) << 4);
                LDMX4(bf[2*p][0], bf[2*p][1], bf[2*p+1][0], bf[2*p+1][1], addr);
            }
#pragma unroll
            for (int mt = 0; mt < 4; mt++)
#pragma unroll
                for (int nt = 0; nt < 4; nt++)
                    MMA_F16(acc[mt][nt], af[mt][0], af[mt][1], af[mt][2], af[mt][3],
                            bf[nt][0], bf[nt][1]);
        }

        if ((s & 3) == 3) {
            const int col0 = (s >> 2) * 128;
            const int rbase = row0 + warp_m * 64 + (lane >> 2);
            const int cb0   = col0 + warp_n * 32 + 2 * (lane & 3);
#pragma unroll
            for (int nt = 0; nt < 4; nt++) {
                const int cc = cb0 + nt * 8;
                const float bv0 = bias[cc], bv1 = bias[cc + 1];
                const float post = (GATHER && cc < 256) ? QSCALE : 1.f;
#pragma unroll
                for (int mt = 0; mt < 4; mt++) {
                    const int r = rbase + mt * 16;
                    float v[4];
#pragma unroll
                    for (int e = 0; e < 4; e++) {
                        float x = acc[mt][nt][e] + ((e & 1) ? bv1 : bv0);
                        if (GELU) {
                            float x3 = x * x * x;
                            x = 0.5f * x * (1.f + tanh_fast(0.7978845608028654f * (x + 0.044715f * x3)));
                        }
                        v[e] = x * post;
                        acc[mt][nt][e] = 0.f;
                    }
                    *(__half2*)(C + (size_t)r * N + cc)       = __floats2half2_rn(v[0], v[1]);
                    *(__half2*)(C + (size_t)(r + 8) * N + cc) = __floats2half2_rn(v[2], v[3]);
                }
            }
        }
    }
}

// ---------------- fp16 mma.sync GEMM (frozen) — used for mlp2 (K=768) ----------
#define STAGE_BYTES 32768
#define NSTAGE      3
#define GEMM_SMEM   (NSTAGE * STAGE_BYTES)

__global__ __launch_bounds__(256, 2)
void gemm_mma(const __half* __restrict__ A, const __half* __restrict__ Bt,
              const float* __restrict__ bias, __half* __restrict__ C,
              int N, int Kd)
{
    extern __shared__ float smem[];
    const uint32_t sbase = smem_u32(smem);
    const int tid  = threadIdx.x;
    const int lane = tid & 31;
    const int wid  = tid >> 5;
    const int warp_m = wid >> 2;
    const int warp_n = wid & 3;
    const int row0 = blockIdx.y * 128;
    const int col0 = blockIdx.x * 128;

    const int mrow = tid >> 3;
    const int c8   = tid & 7;
    const uint32_t swc = (uint32_t)((c8 ^ (mrow & 7)) << 4);

    const __half* arow[4];
    const __half* brow[4];
    uint32_t stA[4];
#pragma unroll
    for (int i = 0; i < 4; i++) {
        const int m = mrow + 32 * i;
        arow[i] = A + (size_t)(row0 + m) * Kd + c8 * 8;
        brow[i] = Bt + (size_t)(col0 + m) * Kd + c8 * 8;
        stA[i] = (uint32_t)(m * 128) + swc;
    }

    const int rA  = warp_m * 64 + (lane & 15);
    const int hiA = lane >> 4;
    const int xA  = lane & 7;
    const int rB  = warp_n * 32 + ((lane >> 4) << 3) + (lane & 7);
    const int hiB = (lane >> 3) & 1;
    const int xB  = lane & 7;

    float acc[4][4][4];
#pragma unroll
    for (int i = 0; i < 4; i++)
#pragma unroll
        for (int j = 0; j < 4; j++)
#pragma unroll
            for (int e = 0; e < 4; e++) acc[i][j][e] = 0.f;

    const int T = Kd >> 6;

#pragma unroll
    for (int s = 0; s < NSTAGE - 1; s++) {
        const int k0 = s * 64;
        const uint32_t so = sbase + s * STAGE_BYTES;
#pragma unroll
        for (int i = 0; i < 4; i++) {
            CP_ASYNC16(so + stA[i],         arow[i] + k0);
            CP_ASYNC16(so + stA[i] + 16384, brow[i] + k0);
        }
        CP_COMMIT();
    }

    for (int t = 0; t < T; ++t) {
        CP_WAIT1();
        __syncthreads();

        const int kt = t + NSTAGE - 1;
        if (kt < T) {
            const int k0 = kt * 64;
            const uint32_t so = sbase + (kt % NSTAGE) * STAGE_BYTES;
#pragma unroll
            for (int i = 0; i < 4; i++) {
                CP_ASYNC16(so + stA[i],         arow[i] + k0);
                CP_ASYNC16(so + stA[i] + 16384, brow[i] + k0);
            }
        }
        CP_COMMIT();

        const uint32_t sa = sbase + (t % NSTAGE) * STAGE_BYTES;
        const uint32_t sb = sa + 16384;
#pragma unroll
        for (int kc = 0; kc < 4; kc++) {
            uint32_t af[4][4];
#pragma unroll
            for (int mt = 0; mt < 4; mt++) {
                const uint32_t addr = sa + (uint32_t)((rA + mt * 16) * 128)
                                    + (uint32_t)((((kc << 1) + hiA) ^ xA) << 4);
                LDMX4(af[mt][0], af[mt][1], af[mt][2], af[mt][3], addr);
            }
            uint32_t bf[4][2];
#pragma unroll
            for (int p = 0; p < 2; p++) {
                const uint32_t addr = sb + (uint32_t)((rB + p * 16) * 128)
                                    + (uint32_t)((((kc << 1) + hiB) ^ xB) << 4);
                LDMX4(bf[2*p][0], bf[2*p][1], bf[2*p+1][0], bf[2*p+1][1], addr);
            }
#pragma unroll
            for (int mt = 0; mt < 4; mt++)
#pragma unroll
                for (int nt = 0; nt < 4; nt++)
                    MMA_F16(acc[mt][nt], af[mt][0], af[mt][1], af[mt][2], af[mt][3],
                            bf[nt][0], bf[nt][1]);
        }
    }

    const int rbase = row0 + warp_m * 64 + (lane >> 2);
    const int cb0   = col0 + warp_n * 32 + 2 * (lane & 3);
#pragma unroll
    for (int nt = 0; nt < 4; nt++) {
        const int cc = cb0 + nt * 8;
        const float bv0 = bias[cc], bv1 = bias[cc + 1];
#pragma unroll
        for (int mt = 0; mt < 4; mt++) {
            const int r = rbase + mt * 16;
            float v[4];
#pragma unroll
            for (int e = 0; e < 4; e++)
                v[e] = acc[mt][nt][e] + ((e & 1) ? bv1 : bv0);
            *(__half2*)(C + (size_t)r * N + cc)       = __floats2half2_rn(v[0], v[1]);
            *(__half2*)(C + (size_t)(r + 8) * N + cc) = __floats2half2_rn(v[2], v[3]);
        }
    }
}

// ---------------- attention v8: fragment-layout bm (coalesced) -----------------
#define AQ_STR 40

__global__ __launch_bounds__(128)
void attn_kernel(const __half* __restrict__ qkv, const __half* __restrict__ bm,
                 __half* __restrict__ o)
{
    const int w = blockIdx.x, head = blockIdx.y;
    const int tid = threadIdx.x;
    const int lane = tid & 31;
    const int wid  = tid >> 5;

    __shared__ __align__(16) __half sQ[64 * AQ_STR];
    __shared__ __align__(16) __half sK[64 * AQ_STR];
    __shared__ __align__(16) __half sV[64 * AQ_STR];   // row-major [s][d]

    {
        const int row  = tid >> 1;
        const int half16 = (tid & 1) * 16;
        const __half* base = qkv + (size_t)(w * 64 + row) * 768 + head * 32 + half16;
        uint4 qv0 = *(const uint4*)(base);
        uint4 qv1 = *(const uint4*)(base + 8);
        uint4 kv0 = *(const uint4*)(base + 256);
        uint4 kv1 = *(const uint4*)(base + 264);
        uint4 vv0 = *(const uint4*)(base + 512);
        uint4 vv1 = *(const uint4*)(base + 520);
        *(uint4*)(sQ + row * AQ_STR + half16)     = qv0;
        *(uint4*)(sQ + row * AQ_STR + half16 + 8) = qv1;
        *(uint4*)(sK + row * AQ_STR + half16)     = kv0;
        *(uint4*)(sK + row * AQ_STR + half16 + 8) = kv1;
        *(uint4*)(sV + row * AQ_STR + half16)     = vv0;
        *(uint4*)(sV + row * AQ_STR + half16 + 8) = vv1;
    }

    // preload bias+mask from FRAGMENT-layout table: 4 coalesced uint4 per thread
    const __half* pb = bm + (size_t)((w & 63) * 8 + head) * 4096;
    float acc[8][4];
#pragma unroll
    for (int c = 0; c < 4; c++) {
        __half v8[8];
        *(uint4*)v8 = *(const uint4*)(pb + c * 1024 + tid * 8);
#pragma unroll
        for (int e = 0; e < 4; e++) {
            acc[2*c][e]     = __half2float(v8[e]);
            acc[2*c + 1][e] = __half2float(v8[4 + e]);
        }
    }
    __syncthreads();

    const uint32_t sQb = smem_u32(sQ);
    const uint32_t sKb = smem_u32(sK);
    const uint32_t sVb = smem_u32(sV);

    const int rA  = (lane & 15);
    const int hiA = lane >> 4;
    const int rBl = ((lane >> 4) << 3) + (lane & 7);
    const int hiB = (lane >> 3) & 1;
    const int rowS = ((lane >> 3) & 1) * 8 + (lane & 7);
    const int colD = (lane >> 4) * 8;

    // ---- QK^T (k=32 -> 2 kc of k16), acc pre-seeded with bias+mask
#pragma unroll
    for (int kc = 0; kc < 2; kc++) {
        uint32_t a0, a1, a2, a3;
        {
            const uint32_t addr = sQb + (uint32_t)(((wid * 16 + rA) * AQ_STR
                                   + kc * 16 + hiA * 8) * 2);
            LDMX4(a0, a1, a2, a3, addr);
        }
#pragma unroll
        for (int p = 0; p < 4; p++) {
            uint32_t b00, b01, b10, b11;
            const uint32_t addr = sKb + (uint32_t)(((p * 16 + rBl) * AQ_STR
                                   + kc * 16 + hiB * 8) * 2);
            LDMX4(b00, b01, b10, b11, addr);
            MMA_F16(acc[2*p],   a0, a1, a2, a3, b00, b01);
            MMA_F16(acc[2*p+1], a0, a1, a2, a3, b10, b11);
        }
    }

    // ---- softmax on fragments (fp32)
    float m0 = -1e30f, m1 = -1e30f;
#pragma unroll
    for (int nt = 0; nt < 8; nt++) {
        m0 = fmaxf(m0, fmaxf(acc[nt][0], acc[nt][1]));
        m1 = fmaxf(m1, fmaxf(acc[nt][2], acc[nt][3]));
    }
    m0 = fmaxf(m0, __shfl_xor_sync(0xffffffffu, m0, 1));
    m0 = fmaxf(m0, __shfl_xor_sync(0xffffffffu, m0, 2));
    m1 = fmaxf(m1, __shfl_xor_sync(0xffffffffu, m1, 1));
    m1 = fmaxf(m1, __shfl_xor_sync(0xffffffffu, m1, 2));

    float s0 = 0.f, s1 = 0.f;
#pragma unroll
    for (int nt = 0; nt < 8; nt++) {
        acc[nt][0] = __expf(acc[nt][0] - m0); s0 += acc[nt][0];
        acc[nt][1] = __expf(acc[nt][1] - m0); s0 += acc[nt][1];
        acc[nt][2] = __expf(acc[nt][2] - m1); s1 += acc[nt][2];
        acc[nt][3] = __expf(acc[nt][3] - m1); s1 += acc[nt][3];
    }
    s0 += __shfl_xor_sync(0xffffffffu, s0, 1);
    s0 += __shfl_xor_sync(0xffffffffu, s0, 2);
    s1 += __shfl_xor_sync(0xffffffffu, s1, 1);
    s1 += __shfl_xor_sync(0xffffffffu, s1, 2);
    const float inv0 = 1.f / s0, inv1 = 1.f / s1;

    // ---- P @ V: P fragments in registers, V via trans-ldmatrix (row-major)
    float oacc[4][4];
#pragma unroll
    for (int nt = 0; nt < 4; nt++)
#pragma unroll
        for (int e = 0; e < 4; e++) oacc[nt][e] = 0.f;

#pragma unroll
    for (int kc = 0; kc < 4; kc++) {
        const uint32_t a0 = h2pack(acc[2*kc][0]   * inv0, acc[2*kc][1]   * inv0);
        const uint32_t a1 = h2pack(acc[2*kc][2]   * inv1, acc[2*kc][3]   * inv1);
        const uint32_t a2 = h2pack(acc[2*kc+1][0] * inv0, acc[2*kc+1][1] * inv0);
        const uint32_t a3 = h2pack(acc[2*kc+1][2] * inv1, acc[2*kc+1][3] * inv1);
#pragma unroll
        for (int p = 0; p < 2; p++) {
            uint32_t b00, b01, b10, b11;
            const uint32_t addr = sVb + (uint32_t)(((kc * 16 + rowS) * AQ_STR
                                   + p * 16 + colD) * 2);
            LDMX4T(b00, b01, b10, b11, addr);
            MMA_F16(oacc[2*p],   a0, a1, a2, a3, b00, b01);
            MMA_F16(oacc[2*p+1], a0, a1, a2, a3, b10, b11);
        }
    }

    const int r0 = wid * 16 + (lane >> 2);
    const int cb = 2 * (lane & 3);
    __half* obase = o + (size_t)(w * 64 + r0) * 256 + head * 32;
#pragma unroll
    for (int nt = 0; nt < 4; nt++) {
        *(__half2*)(obase + 8 * nt + cb) = __floats2half2_rn(oacc[nt][0], oacc[nt][1]);
        *(__half2*)(obase + 8 * 256 + 8 * nt + cb) = __floats2half2_rn(oacc[nt][2], oacc[nt][3]);
    }
}

// ---------------- LayerNorm: warp-per-row, fp16 inputs (frozen R10) ------------
__global__ __launch_bounds__(256)
void ln1_kernel(const __half* __restrict__ X, const float* __restrict__ g,
                const float* __restrict__ b, const float* __restrict__ query,
                __half* __restrict__ out)
{
    const int row  = blockIdx.x * 8 + (threadIdx.x >> 5);
    const int lane = threadIdx.x & 31;
    const int c0   = lane * 8;

    __half x8[8];
    *(uint4*)(x8) = *(const uint4*)(X + (size_t)row * CH + c0);
    float v[8];
#pragma unroll
    for (int i = 0; i < 8; i++) v[i] = __half2float(x8[i]);

    float s = 0.f, s2 = 0.f;
#pragma unroll
    for (int i = 0; i < 8; i++) { s += v[i]; s2 += v[i] * v[i]; }
#pragma unroll
    for (int off = 16; off; off >>= 1) {
        s  += __shfl_xor_sync(0xffffffffu, s,  off);
        s2 += __shfl_xor_sync(0xffffffffu, s2, off);
    }
    const float mean = s * (1.f / 256.f);
    const float rstd = rsqrtf(s2 * (1.f / 256.f) - mean * mean + 1e-5f);

    float gv[8], bv[8], qv[8];
    *(float4*)(gv)     = *(const float4*)(g + c0);
    *(float4*)(gv + 4) = *(const float4*)(g + c0 + 4);
    *(float4*)(bv)     = *(const float4*)(b + c0);
    *(float4*)(bv + 4) = *(const float4*)(b + c0 + 4);
    const float* qr = query + (size_t)map_row(row) * CH + c0;
    *(float4*)(qv)     = *(const float4*)(qr);
    *(float4*)(qv + 4) = *(const float4*)(qr + 4);

    __half h8[8];
#pragma unroll
    for (int i = 0; i < 8; i++)
        h8[i] = __float2half((v[i] - mean) * rstd * gv[i] + bv[i] + qv[i]);
    *(uint4*)(out + (size_t)row * CH + c0) = *(uint4*)h8;
}

__global__ __launch_bounds__(256)
void ln2_kernel(const __half* __restrict__ X, const float* __restrict__ g,
                const float* __restrict__ b, const __half* __restrict__ x2,
                float* __restrict__ out)
{
    const int row  = blockIdx.x * 8 + (threadIdx.x >> 5);
    const int lane = threadIdx.x & 31;
    const int c0   = lane * 8;

    __half x8[8];
    *(uint4*)(x8) = *(const uint4*)(X + (size_t)row * CH + c0);
    float v[8];
#pragma unroll
    for (int i = 0; i < 8; i++) v[i] = __half2float(x8[i]);

    float s = 0.f, s2 = 0.f;
#pragma unroll
    for (int i = 0; i < 8; i++) { s += v[i]; s2 += v[i] * v[i]; }
#pragma unroll
    for (int off = 16; off; off >>= 1) {
        s  += __shfl_xor_sync(0xffffffffu, s,  off);
        s2 += __shfl_xor_sync(0xffffffffu, s2, off);
    }
    const float mean = s * (1.f / 256.f);
    const float rstd = rsqrtf(s2 * (1.f / 256.f) - mean * mean + 1e-5f);

    float gv[8], bv[8];
    *(float4*)(gv)     = *(const float4*)(g + c0);
    *(float4*)(gv + 4) = *(const float4*)(g + c0 + 4);
    *(float4*)(bv)     = *(const float4*)(b + c0);
    *(float4*)(bv + 4) = *(const float4*)(b + c0 + 4);
    __half r8[8];
    *(uint4*)(r8) = *(const uint4*)(x2 + (size_t)row * CH + c0);

    float o8[8];
#pragma unroll
    for (int i = 0; i < 8; i++)
        o8[i] = (v[i] - mean) * rstd * gv[i] + bv[i] + __half2float(r8[i]);
    float* op = out + (size_t)map_row(row) * CH + c0;
    *(float4*)(op)     = *(float4*)(o8);
    *(float4*)(op + 4) = *(float4*)(o8 + 4);
}

// ---------------- weight prep ----------------------------------------------------
__global__ __launch_bounds__(256)
void prep_kernel(const float* __restrict__ wq, const float* __restrict__ wk,
                 const float* __restrict__ wv, const float* __restrict__ bq,
                 const float* __restrict__ bk, const float* __restrict__ bv,
                 const float* __restrict__ wo, const float* __restrict__ w1,
                 const float* __restrict__ w2,
                 __half* __restrict__ wqkvT, float* __restrict__ bqkv,
                 __half* __restrict__ woT, __half* __restrict__ w1T,
                 __half* __restrict__ w2T)
{
    int i = blockIdx.x * 256 + threadIdx.x;
    if (i < 196608) {
        int n = i >> 8, k = i & 255;
        float v = (n < 256) ? wq[k * 256 + n]
                : (n < 512) ? wk[k * 256 + (n - 256)]
                            : wv[k * 256 + (n - 512)];
        wqkvT[i] = __float2half(v);
    } else if (i < 262144) {
        int j = i - 196608; int n = j >> 8, k = j & 255;
        woT[j] = __float2half(wo[k * 256 + n]);
    } else if (i < 458752) {
        int j = i - 262144; int n = j >> 8, k = j & 255;
        w1T[j] = __float2half(w1[k * 768 + n]);
    } else if (i < 655360) {
        int j = i - 458752; int n = j / 768, k = j - n * 768;
        w2T[j] = __float2half(w2[k * 256 + n]);
    } else if (i < 656128) {
        int n = i - 655360;
        bqkv[n] = (n < 256) ? bq[n] : (n < 512) ? bk[n - 256] : bv[n - 512];
    }
}

// ---------------- bias+mask table: FRAGMENT layout -----------------------------
// pbm[wi][h][chunk c][tid][j] with nt = 2c + (j>>2), e = j&3:
//   row = wid*16 + (lane>>2) + (e>=2 ? 8 : 0),  col = 8*nt + 2*(lane&3) + (e&1)
__global__ __launch_bounds__(256)
void prep_bm_kernel(const float* __restrict__ rpe, const float* __restrict__ mask,
                    const int* __restrict__ rel, __half* __restrict__ bm)
{
    int idx = blockIdx.x * 256 + threadIdx.x;      // 0 .. 2M-1
    int wi  = idx >> 15;
    int rem = idx & 32767;
    int h   = rem >> 12;
    int r2  = rem & 4095;
    int c   = r2 >> 10;
    int r3  = r2 & 1023;
    int tid = r3 >> 3;
    int j   = r3 & 7;
    int nt  = c * 2 + (j >> 2);
    int e   = j & 3;
    int lane = tid & 31, wid = tid >> 5;
    int row = wid * 16 + (lane >> 2) + ((e & 2) ? 8 : 0);
    int col = nt * 8 + 2 * (lane & 3) + (e & 1);
    int ts  = row * 64 + col;
    bm[idx] = __float2half(rpe[rel[ts] * NHEAD + h] + fmaxf(mask[wi * 4096 + ts], -30000.f));
}

// ---------------- launch ----------------------------------------------------------
extern "C" void kernel_launch(void* const* d_in, const int* in_sizes, int n_in,
                              void* d_out, int out_size)
{
    const float* query = (const float*)d_in[0];
    const float* wq = (const float*)d_in[1];  const float* bq = (const float*)d_in[2];
    const float* wk = (const float*)d_in[3];  const float* bk = (const float*)d_in[4];
    const float* wv = (const float*)d_in[5];  const float* bv = (const float*)d_in[6];
    const float* wo = (const float*)d_in[7];  const float* bo = (const float*)d_in[8];
    const float* rpe = (const float*)d_in[9];
    const float* ln1g = (const float*)d_in[10]; const float* ln1b = (const float*)d_in[11];
    const float* ln2g = (const float*)d_in[12]; const float* ln2b = (const float*)d_in[13];
    const float* w1 = (const float*)d_in[14]; const float* b1 = (const float*)d_in[15];
    const float* w2 = (const float*)d_in[16]; const float* b2 = (const float*)d_in[17];
    const float* amask = (const float*)d_in[18];
    const int*   rel   = (const int*)d_in[19];
    float* out = (float*)d_out;

    float *qkvf, *hf, *bqkv;
    __half *oh, *x2h, *wqkvT, *woT, *w1T, *w2T, *bm;
    cudaGetSymbolAddress((void**)&qkvf,  g_qkv);
    cudaGetSymbolAddress((void**)&hf,    g_h);
    cudaGetSymbolAddress((void**)&oh,    g_oh);
    cudaGetSymbolAddress((void**)&x2h,   g_x2h);
    cudaGetSymbolAddress((void**)&wqkvT, g_wqkvT);
    cudaGetSymbolAddress((void**)&bqkv,  g_bqkv);
    cudaGetSymbolAddress((void**)&woT,   g_woT);
    cudaGetSymbolAddress((void**)&w1T,   g_w1T);
    cudaGetSymbolAddress((void**)&w2T,   g_w2T);
    cudaGetSymbolAddress((void**)&bm,    g_bm);
    __half* qkvh = (__half*)qkvf;   // fp16 qkv / mlp1 alias
    __half* hh   = (__half*)hf;     // fp16 proj-out alias

    cudaFuncSetAttribute(gemm_nres<true,  false, 6>, cudaFuncAttributeMaxDynamicSharedMemorySize, NRES_SMEM);
    cudaFuncSetAttribute(gemm_nres<false, false, 2>, cudaFuncAttributeMaxDynamicSharedMemorySize, NRES_SMEM);
    cudaFuncSetAttribute(gemm_nres<false, true,  6>, cudaFuncAttributeMaxDynamicSharedMemorySize, NRES_SMEM);
    cudaFuncSetAttribute(gemm_mma, cudaFuncAttributeMaxDynamicSharedMemorySize, GEMM_SMEM);

    // prep: weights->fp16, bias/mask table (fragment layout)
    prep_kernel<<<2563, 256>>>(wq, wk, wv, bq, bk, bv, wo, w1, w2,
                               wqkvT, bqkv, woT, w1T, w2T);
    prep_bm_kernel<<<8192, 256>>>(rpe, amask, rel, bm);

    // fused QKV projection (A gathered+converted from fp32 query in-prologue)
    gemm_nres<true,  false, 6><<<1024, 256, NRES_SMEM>>>(query, wqkvT, bqkv, qkvh);

    // windowed attention -> fp16 oh
    attn_kernel<<<dim3(TOTW, NHEAD), 128>>>(qkvh, bm, oh);

    // output projection (A-resident) -> fp16 hh
    gemm_nres<false, false, 2><<<1024, 256, NRES_SMEM>>>(oh, woT, bo, hh);

    // LN1 + residual -> fp16 x2
    ln1_kernel<<<MROWS / 8, 256>>>(hh, ln1g, ln1b, query, x2h);

    // MLP: gelu(x2@w1+b1) -> fp16 (A-resident); @w2+b2 (K=768) -> fp16 oh
    gemm_nres<false, true,  6><<<1024, 256, NRES_SMEM>>>(x2h, w1T, b1, qkvh);
    gemm_mma<<<dim3(2, 1024), 256, GEMM_SMEM>>>(qkvh, w2T, b2, oh, 256, 768);

    // LN2 + residual, scatter to output
    ln2_kernel<<<MROWS / 8, 256>>>(oh, ln2g, ln2b, x2h, out);
}